// round 5
// baseline (speedup 1.0000x reference)
#include <cuda_runtime.h>

#define LAYERS 8
#define T      512
#define B      64
#define H      256
#define G      1024        // 4H
#define VOCAB  23
#define EMB    16
#define NC     16          // CTAs per layer
#define JT     64          // gate rows per CTA
#define KC     32          // k chunk

// -------- persistent device scratch (no allocations allowed) --------
__device__ float g_hseq[(size_t)LAYERS * T * B * H];   // per-layer output sequences (~256 MB)
__device__ float g_table[VOCAB * G];                   // fused layer-0 input+bias table
__device__ int   g_done[LAYERS * T];                   // per (layer, t) completion counters

// -------- helpers --------
__device__ __forceinline__ unsigned long long fma2(unsigned long long a,
                                                   unsigned long long b,
                                                   unsigned long long c) {
    unsigned long long d;
    asm("fma.rn.f32x2 %0, %1, %2, %3;" : "=l"(d) : "l"(a), "l"(b), "l"(c));
    return d;
}
__device__ __forceinline__ float sigm(float x)     { return 1.f / (1.f + __expf(-x)); }
__device__ __forceinline__ float tanhfast(float x) { return 1.f - 2.f / (__expf(2.f * x) + 1.f); }

__device__ __forceinline__ void wait_done(int idx) {
    if (threadIdx.x == 0) {
        volatile int* p = &g_done[idx];
        while (*p < NC) __nanosleep(64);
    }
    __syncthreads();
}

// GEMM pass: acc[4][2] (4 b-rows x 4 j packed as 2 f32x2) += A[64 x 256] * WsT slice.
// A rows are staged into smem duplicated as (a,a) float2; WsT is [k][jl] (64 cols).
__device__ __forceinline__ void gemm_pass(
    const float* __restrict__ A, const float* __restrict__ WsT,
    float2* __restrict__ As2, unsigned long long (&acc)[4][2],
    int tx, int ty, int tid)
{
    const int b  = tid >> 2;          // 0..63
    const int k0 = (tid & 3) << 3;    // 0,8,16,24
    const float* arow = A + b * H;

    float4 r0 = *(const float4*)(arow + k0);
    float4 r1 = *(const float4*)(arow + k0 + 4);
    {
        float2* dst = As2;            // buffer 0
        dst[(k0 + 0) * 66 + b] = make_float2(r0.x, r0.x);
        dst[(k0 + 1) * 66 + b] = make_float2(r0.y, r0.y);
        dst[(k0 + 2) * 66 + b] = make_float2(r0.z, r0.z);
        dst[(k0 + 3) * 66 + b] = make_float2(r0.w, r0.w);
        dst[(k0 + 4) * 66 + b] = make_float2(r1.x, r1.x);
        dst[(k0 + 5) * 66 + b] = make_float2(r1.y, r1.y);
        dst[(k0 + 6) * 66 + b] = make_float2(r1.z, r1.z);
        dst[(k0 + 7) * 66 + b] = make_float2(r1.w, r1.w);
    }
    __syncthreads();

#pragma unroll 1
    for (int kc = 0; kc < H; kc += KC) {
        const int buf = (kc >> 5) & 1;
        if (kc + KC < H) {  // prefetch next chunk into registers (hides L2 latency)
            r0 = *(const float4*)(arow + kc + KC + k0);
            r1 = *(const float4*)(arow + kc + KC + k0 + 4);
        }
        const float2* Ab = As2 + buf * (KC * 66);
#pragma unroll
        for (int k = 0; k < KC; ++k) {
            ulonglong2 a01 = *(const ulonglong2*)(Ab + k * 66 + ty * 4);
            ulonglong2 a23 = *(const ulonglong2*)(Ab + k * 66 + ty * 4 + 2);
            ulonglong2 w   = *(const ulonglong2*)(WsT + (kc + k) * 64 + tx * 4);
            acc[0][0] = fma2(a01.x, w.x, acc[0][0]);
            acc[0][1] = fma2(a01.x, w.y, acc[0][1]);
            acc[1][0] = fma2(a01.y, w.x, acc[1][0]);
            acc[1][1] = fma2(a01.y, w.y, acc[1][1]);
            acc[2][0] = fma2(a23.x, w.x, acc[2][0]);
            acc[2][1] = fma2(a23.x, w.y, acc[2][1]);
            acc[3][0] = fma2(a23.y, w.x, acc[3][0]);
            acc[3][1] = fma2(a23.y, w.y, acc[3][1]);
        }
        if (kc + KC < H) {
            float2* dst = As2 + ((buf ^ 1) * (KC * 66));
            dst[(k0 + 0) * 66 + b] = make_float2(r0.x, r0.x);
            dst[(k0 + 1) * 66 + b] = make_float2(r0.y, r0.y);
            dst[(k0 + 2) * 66 + b] = make_float2(r0.z, r0.z);
            dst[(k0 + 3) * 66 + b] = make_float2(r0.w, r0.w);
            dst[(k0 + 4) * 66 + b] = make_float2(r1.x, r1.x);
            dst[(k0 + 5) * 66 + b] = make_float2(r1.y, r1.y);
            dst[(k0 + 6) * 66 + b] = make_float2(r1.z, r1.z);
            dst[(k0 + 7) * 66 + b] = make_float2(r1.w, r1.w);
        }
        __syncthreads();
    }
}

// -------- prelude kernels --------
__global__ void zero_done_kernel() {
    int i = blockIdx.x * blockDim.x + threadIdx.x;
    if (i < LAYERS * T) g_done[i] = 0;
}

__global__ void build_table_kernel(const float* __restrict__ emb,
                                   const float* __restrict__ Wih0,
                                   const float* __restrict__ bih,
                                   const float* __restrict__ bhh) {
    int idx = blockIdx.x * blockDim.x + threadIdx.x;
    if (idx >= VOCAB * G) return;
    int v = idx / G, j = idx % G;
    float s = bih[j] + bhh[j];
#pragma unroll
    for (int e = 0; e < EMB; ++e) s += emb[v * EMB + e] * Wih0[j * EMB + e];
    g_table[idx] = s;
}

// -------- main persistent wavefront kernel --------
// grid = LAYERS*NC CTAs, all co-resident (128 <= 148 SMs at 1 CTA/SM).
// smem (floats): WihS[256*64] | WhhS[256*64] | As2 (2*32*66 float2, aliased by Gx[64*66]) | cst[64*16] | biasS[64]
#define SM_WIH   0
#define SM_WHH   (256 * 64)
#define SM_AS2   (2 * 256 * 64)
#define SM_CST   (SM_AS2 + 2 * KC * 66 * 2)
#define SM_BIAS  (SM_CST + 64 * 16)
#define SM_FLOATS (SM_BIAS + 64)
#define SM_BYTES  (SM_FLOATS * 4)

extern "C" __global__ void __launch_bounds__(256, 1)
lstm_main_kernel(const int* __restrict__ x,
                 const float* __restrict__ Wih_rest,
                 const float* __restrict__ Whh,
                 const float* __restrict__ bih,
                 const float* __restrict__ bhh)
{
    extern __shared__ float smem[];
    const int tid = threadIdx.x;
    const int l   = blockIdx.x / NC;
    const int c   = blockIdx.x % NC;
    const int tx  = tid & 15;    // j tile (16 x 4 = 64)
    const int ty  = tid >> 4;    // b tile (16 x 4 = 64)

    float*  WihS  = smem + SM_WIH;                 // [k][jl] transposed (l>=1)
    float*  WhhS  = smem + SM_WHH;                 // [k][jl] transposed
    float2* As2   = (float2*)(smem + SM_AS2);      // staging, double buffered, duplicated pairs
    float*  Gx    = smem + SM_AS2;                 // gate exchange [64][66] (aliases As2)
    float*  cst   = smem + SM_CST;                 // cell state [b*16+hl]
    float*  biasS = smem + SM_BIAS;
    float*  tabS  = smem + SM_WIH;                 // l==0: token table slice [VOCAB][64]

    // ---- load resident weights (transposed: [k][jl]) ----
    if (l == 0) {
        for (int idx = tid; idx < VOCAB * JT; idx += 256) {
            int v = idx / JT, jl = idx % JT;
            int jg = (jl >> 4) * H + c * 16 + (jl & 15);
            tabS[idx] = g_table[v * G + jg];
        }
    } else {
        const float* Wl = Wih_rest + (size_t)(l - 1) * G * H;
        for (int idx = tid; idx < H * JT; idx += 256) {
            int k = idx / JT, jl = idx % JT;
            int jg = (jl >> 4) * H + c * 16 + (jl & 15);
            WihS[idx] = Wl[(size_t)jg * H + k];
        }
        if (tid < JT) {
            int jg = (tid >> 4) * H + c * 16 + (tid & 15);
            biasS[tid] = bih[l * G + jg] + bhh[l * G + jg];
        }
    }
    {
        const float* Wl = Whh + (size_t)l * G * H;
        for (int idx = tid; idx < H * JT; idx += 256) {
            int k = idx / JT, jl = idx % JT;
            int jg = (jl >> 4) * H + c * 16 + (jl & 15);
            WhhS[idx] = Wl[(size_t)jg * H + k];
        }
    }
    __syncthreads();

    float*       hown = g_hseq + (size_t)l * T * B * H;
    const float* hin  = (l > 0) ? (g_hseq + (size_t)(l - 1) * T * B * H) : (const float*)0;

    for (int t = 0; t < T; ++t) {
        unsigned long long acc[4][2];
        if (l == 0) {
#pragma unroll
            for (int r = 0; r < 4; ++r) {
                int bb  = ty * 4 + r;
                int tok = x[bb * T + t];
                ulonglong2 p = *(const ulonglong2*)(tabS + tok * JT + tx * 4);
                acc[r][0] = p.x; acc[r][1] = p.y;
            }
        } else {
            ulonglong2 p = *(const ulonglong2*)(biasS + tx * 4);
#pragma unroll
            for (int r = 0; r < 4; ++r) { acc[r][0] = p.x; acc[r][1] = p.y; }
        }

        // recurrent pass first (own h_{t-1} is ready earlier than producer's h_t)
        if (t > 0) {
            wait_done(l * T + (t - 1));
            gemm_pass(hown + (size_t)(t - 1) * B * H, WhhS, As2, acc, tx, ty, tid);
        }
        if (l > 0) {
            wait_done((l - 1) * T + t);
            gemm_pass(hin + (size_t)t * B * H, WihS, As2, acc, tx, ty, tid);
        }

        // exchange gates through smem (aliases As2 — all GEMM reads done after its final sync)
#pragma unroll
        for (int r = 0; r < 4; ++r) {
            int bb = ty * 4 + r;
            *(unsigned long long*)(Gx + bb * 66 + tx * 4)     = acc[r][0];
            *(unsigned long long*)(Gx + bb * 66 + tx * 4 + 2) = acc[r][1];
        }
        __syncthreads();

        // elementwise LSTM cell update for this CTA's 16 hidden units x 64 batch
        float* hout = hown + (size_t)t * B * H;
#pragma unroll
        for (int i = 0; i < 4; ++i) {
            int q  = i * 256 + tid;       // q = b*16 + hl
            int bb = q >> 4, hl = q & 15;
            float ig = Gx[bb * 66 + hl];
            float fg = Gx[bb * 66 + 16 + hl];
            float gg = Gx[bb * 66 + 32 + hl];
            float og = Gx[bb * 66 + 48 + hl];
            float cv = (t == 0) ? 0.f : cst[q];
            float cn = sigm(fg) * cv + sigm(ig) * tanhfast(gg);
            cst[q] = cn;
            hout[bb * H + c * 16 + hl] = sigm(og) * tanhfast(cn);
        }
        __threadfence();
        __syncthreads();
        if (tid == 0) atomicAdd(&g_done[l * T + t], 1);
    }
}

// -------- final FC: out[b,t,v] = h7[b,t,:] @ fc_w[v,:] + fc_b[v] --------
#define FCROWS 16
__global__ void __launch_bounds__(256)
fc_kernel(const float* __restrict__ fcw, const float* __restrict__ fcb,
          float* __restrict__ out)
{
    __shared__ float hs[FCROWS][256];
    __shared__ float ws[256][24];   // fc_w transposed, padded
    __shared__ float bs[24];
    const int tid = threadIdx.x;

    for (int idx = tid; idx < VOCAB * H; idx += 256) {
        int v = idx / H, k = idx % H;
        ws[k][v] = fcw[idx];
    }
    if (tid < VOCAB) bs[tid] = fcb[tid];

    const int r0 = blockIdx.x * FCROWS;
    const float* h7 = g_hseq + (size_t)7 * T * B * H;
    for (int i = 0; i < FCROWS; ++i) {
        int rg = r0 + i;
        int b = rg >> 9, t = rg & 511;
        hs[i][tid] = h7[((size_t)t * B + b) * H + tid];
    }
    __syncthreads();

    for (int q = tid; q < FCROWS * VOCAB; q += 256) {
        int r = q / VOCAB, v = q % VOCAB;
        float s = bs[v];
#pragma unroll 8
        for (int k = 0; k < H; ++k) s += hs[r][k] * ws[k][v];
        out[(size_t)(r0 + r) * VOCAB + v] = s;
    }
}

// -------- launch --------
extern "C" void kernel_launch(void* const* d_in, const int* in_sizes, int n_in,
                              void* d_out, int out_size)
{
    const int*   x        = (const int*)d_in[0];
    const float* emb      = (const float*)d_in[1];
    const float* Wih0     = (const float*)d_in[2];
    const float* Wih_rest = (const float*)d_in[3];
    const float* Whh      = (const float*)d_in[4];
    const float* bih      = (const float*)d_in[5];
    const float* bhh      = (const float*)d_in[6];
    const float* fcw      = (const float*)d_in[7];
    const float* fcb      = (const float*)d_in[8];
    float*       out      = (float*)d_out;

    cudaFuncSetAttribute(lstm_main_kernel,
                         cudaFuncAttributeMaxDynamicSharedMemorySize, SM_BYTES);

    zero_done_kernel<<<16, 256>>>();
    build_table_kernel<<<(VOCAB * G + 255) / 256, 256>>>(emb, Wih0, bih, bhh);
    lstm_main_kernel<<<LAYERS * NC, 256, SM_BYTES>>>(x, Wih_rest, Whh, bih, bhh);
    fc_kernel<<<(B * T) / FCROWS, 256>>>(fcw, fcb, out);
}

// round 6
// speedup vs baseline: 1.3685x; 1.3685x over previous
#include <cuda_runtime.h>

#define LAYERS 8
#define T      512
#define B      64
#define H      256
#define G      1024        // 4H
#define VOCAB  23
#define EMB    16
#define NC     16          // CTAs per layer
#define JT     64          // gate rows per CTA
#define THR    128

typedef unsigned long long ull;

// -------- persistent device scratch --------
__device__ float g_hseq[(size_t)LAYERS * T * H * B];   // [l][t][k(H)][b]  (~256 MB)
__device__ float g_table[VOCAB * G];                   // fused layer-0 input+bias table
__device__ int   g_done[LAYERS * T];

// -------- helpers --------
__device__ __forceinline__ ull fma2(ull a, ull b, ull c) {
    ull d; asm("fma.rn.f32x2 %0, %1, %2, %3;" : "=l"(d) : "l"(a), "l"(b), "l"(c));
    return d;
}
__device__ __forceinline__ ull add2(ull a, ull b) {
    ull d; asm("add.rn.f32x2 %0, %1, %2;" : "=l"(d) : "l"(a), "l"(b));
    return d;
}
__device__ __forceinline__ ull pack2(float v) {
    ull d; asm("mov.b64 %0, {%1, %1};" : "=l"(d) : "f"(v));
    return d;
}
__device__ __forceinline__ float sigm(float x)     { return 1.f / (1.f + __expf(-x)); }
__device__ __forceinline__ float tanhfast(float x) { return 1.f - 2.f / (__expf(2.f * x) + 1.f); }

__device__ __forceinline__ void wait_done(int idx) {
    if (threadIdx.x == 0) {
        volatile int* p = &g_done[idx];
        while (*p < NC) __nanosleep(32);
    }
    __syncthreads();
}

// -------- smem layout (floats) --------
#define SM_WHH   0
#define SM_WIH   16384
#define SM_AST   32768                 // [2 grp][2 buf][32 k][64 b] = 8192
#define SM_GX    40960                 // [64 b][68] = 4352
#define SM_CST   45312                 // [64 b][16 hl] = 1024
#define SM_BIAS  46336                 // 64
#define SM_TOK   46400                 // 64 ints
#define SM_FLOATS 46464
#define SM_BYTES  (SM_FLOATS * 4)

// -------- prelude kernels --------
__global__ void zero_done_kernel() {
    int i = blockIdx.x * blockDim.x + threadIdx.x;
    if (i < LAYERS * T) g_done[i] = 0;
}

__global__ void build_table_kernel(const float* __restrict__ emb,
                                   const float* __restrict__ Wih0,
                                   const float* __restrict__ bih,
                                   const float* __restrict__ bhh) {
    int idx = blockIdx.x * blockDim.x + threadIdx.x;
    if (idx >= VOCAB * G) return;
    int v = idx / G, j = idx % G;
    float s = bih[j] + bhh[j];
#pragma unroll
    for (int e = 0; e < EMB; ++e) s += emb[v * EMB + e] * Wih0[j * EMB + e];
    g_table[idx] = s;
}

// One K-half GEMM pass: acc += A[khalf, b] * W[khalf, j] for this thread's 8b x 8j tile.
// A is global [256][64]; staged to smem in 32-k double-buffered chunks.
__device__ __forceinline__ void gemm_half(
    const float* __restrict__ Aglob, const float* __restrict__ Ws,
    float* __restrict__ AstBase,
    ull (&accA)[8][2], ull (&accB)[8][2],
    int kg, int jg, int bg, int tid)
{
    const int ltid = tid & 63;
    const float* src = Aglob + kg * (128 * 64);
    float* base = AstBase + kg * 4096;      // 2 buffers x 2048 floats for this k-group

    // stage chunk 0
    {
        const float4* s = (const float4*)src;
        float4* d = (float4*)base;
#pragma unroll
        for (int u = 0; u < 8; ++u) d[ltid + u * 64] = s[ltid + u * 64];
    }
    __syncthreads();

#pragma unroll 1
    for (int r = 0; r < 4; ++r) {
        float4 pf0, pf1, pf2, pf3, pf4, pf5, pf6, pf7;
        if (r < 3) {    // register prefetch of next chunk
            const float4* s = (const float4*)(src + (r + 1) * 2048);
            pf0 = s[ltid];        pf1 = s[ltid + 64];
            pf2 = s[ltid + 128];  pf3 = s[ltid + 192];
            pf4 = s[ltid + 256];  pf5 = s[ltid + 320];
            pf6 = s[ltid + 384];  pf7 = s[ltid + 448];
        }
        const float* Ab = base + (r & 1) * 2048;
        const float* Wk = Ws + (kg * 128 + r * 32) * 64;
#pragma unroll 4
        for (int k = 0; k < 32; ++k) {
            ulonglong2 wA = *(const ulonglong2*)(Wk + k * 64 + jg * 4);
            ulonglong2 wB = *(const ulonglong2*)(Wk + k * 64 + 32 + jg * 4);
            float4 a0 = *(const float4*)(Ab + k * 64 + bg * 8);
            float4 a1 = *(const float4*)(Ab + k * 64 + bg * 8 + 4);
#define ROWF(rr, av) { ull p = pack2(av); \
            accA[rr][0] = fma2(p, wA.x, accA[rr][0]); \
            accA[rr][1] = fma2(p, wA.y, accA[rr][1]); \
            accB[rr][0] = fma2(p, wB.x, accB[rr][0]); \
            accB[rr][1] = fma2(p, wB.y, accB[rr][1]); }
            ROWF(0, a0.x) ROWF(1, a0.y) ROWF(2, a0.z) ROWF(3, a0.w)
            ROWF(4, a1.x) ROWF(5, a1.y) ROWF(6, a1.z) ROWF(7, a1.w)
#undef ROWF
        }
        if (r < 3) {
            float4* d = (float4*)(base + ((r + 1) & 1) * 2048);
            d[ltid]       = pf0;  d[ltid + 64]  = pf1;
            d[ltid + 128] = pf2;  d[ltid + 192] = pf3;
            d[ltid + 256] = pf4;  d[ltid + 320] = pf5;
            d[ltid + 384] = pf6;  d[ltid + 448] = pf7;
        }
        __syncthreads();
    }
}

// -------- main persistent wavefront kernel --------
extern "C" __global__ void __launch_bounds__(THR, 1)
lstm_main_kernel(const int* __restrict__ x,
                 const float* __restrict__ Wih_rest,
                 const float* __restrict__ Whh,
                 const float* __restrict__ bih,
                 const float* __restrict__ bhh)
{
    extern __shared__ float smem[];
    const int tid  = threadIdx.x;
    const int l    = blockIdx.x / NC;
    const int c    = blockIdx.x % NC;
    const int warp = tid >> 5, lane = tid & 31;
    const int kg   = warp >> 1;                    // k-half 0/1
    const int jg   = lane & 7;                     // owns j in {4jg..4jg+3} U {32+4jg..+3}
    const int bg   = (lane >> 3) + (warp & 1) * 4; // 0..7 -> b = 8*bg..+7

    float* WhhS  = smem + SM_WHH;
    float* WihS  = smem + SM_WIH;    // l==0: token table slice [VOCAB][64]
    float* Ast   = smem + SM_AST;
    float* Gx    = smem + SM_GX;     // [64][68]
    float* cst   = smem + SM_CST;    // [b*16+hl]
    float* biasS = smem + SM_BIAS;
    int*   tokI  = (int*)(smem + SM_TOK);
    float* tabS  = WihS;

    // ---- resident weights (transposed [k][jl]) ----
    {
        const float* Wl = Whh + (size_t)l * G * H;
        for (int idx = tid; idx < H * JT; idx += THR) {
            int k = idx >> 6, jl = idx & 63;
            int jgl = (jl >> 4) * H + c * 16 + (jl & 15);
            WhhS[idx] = Wl[(size_t)jgl * H + k];
        }
    }
    if (l == 0) {
        for (int idx = tid; idx < VOCAB * JT; idx += THR) {
            int v = idx / JT, jl = idx % JT;
            int jgl = (jl >> 4) * H + c * 16 + (jl & 15);
            tabS[idx] = g_table[v * G + jgl];
        }
    } else {
        const float* Wl = Wih_rest + (size_t)(l - 1) * G * H;
        for (int idx = tid; idx < H * JT; idx += THR) {
            int k = idx >> 6, jl = idx & 63;
            int jgl = (jl >> 4) * H + c * 16 + (jl & 15);
            WihS[idx] = Wl[(size_t)jgl * H + k];
        }
        if (tid < JT) {
            int jgl = (tid >> 4) * H + c * 16 + (tid & 15);
            biasS[tid] = bih[l * G + jgl] + bhh[l * G + jgl];
        }
    }
    __syncthreads();

    float*       hown = g_hseq + (size_t)l * T * H * B;
    const float* hin  = (l > 0) ? (g_hseq + (size_t)(l - 1) * T * H * B) : (const float*)0;

    for (int t = 0; t < T; ++t) {
        ull accA[8][2], accB[8][2];

        // ---- accumulator init (bias / layer-0 token table; kg1 starts at zero) ----
        if (l == 0) {
            if (tid < 64) tokI[tid] = x[tid * T + t];
            __syncthreads();
            if (kg == 0) {
#pragma unroll
                for (int r = 0; r < 8; ++r) {
                    int tk = tokI[bg * 8 + r];
                    ulonglong2 pA = *(const ulonglong2*)(tabS + tk * 64 + jg * 4);
                    ulonglong2 pB = *(const ulonglong2*)(tabS + tk * 64 + 32 + jg * 4);
                    accA[r][0] = pA.x; accA[r][1] = pA.y;
                    accB[r][0] = pB.x; accB[r][1] = pB.y;
                }
            } else {
#pragma unroll
                for (int r = 0; r < 8; ++r) { accA[r][0]=accA[r][1]=accB[r][0]=accB[r][1]=0ULL; }
            }
        } else {
            if (kg == 0) {
                ulonglong2 pA = *(const ulonglong2*)(biasS + jg * 4);
                ulonglong2 pB = *(const ulonglong2*)(biasS + 32 + jg * 4);
#pragma unroll
                for (int r = 0; r < 8; ++r) {
                    accA[r][0] = pA.x; accA[r][1] = pA.y;
                    accB[r][0] = pB.x; accB[r][1] = pB.y;
                }
            } else {
#pragma unroll
                for (int r = 0; r < 8; ++r) { accA[r][0]=accA[r][1]=accB[r][0]=accB[r][1]=0ULL; }
            }
        }

        // ---- recurrent pass, then input pass (accumulate in registers) ----
        if (t > 0) {
            wait_done(l * T + (t - 1));
            gemm_half(hown + (size_t)(t - 1) * H * B, WhhS, Ast, accA, accB, kg, jg, bg, tid);
        }
        if (l > 0) {
            wait_done((l - 1) * T + t);
            gemm_half(hin + (size_t)t * H * B, WihS, Ast, accA, accB, kg, jg, bg, tid);
        }

        // ---- split-K reduction into Gx [64][68] ----
        if (kg == 0) {
#pragma unroll
            for (int r = 0; r < 8; ++r) {
                int b = bg * 8 + r;
                *(ulonglong2*)(Gx + b * 68 + jg * 4)      = make_ulonglong2(accA[r][0], accA[r][1]);
                *(ulonglong2*)(Gx + b * 68 + 32 + jg * 4) = make_ulonglong2(accB[r][0], accB[r][1]);
            }
        }
        __syncthreads();
        if (kg == 1) {
#pragma unroll
            for (int r = 0; r < 8; ++r) {
                int b = bg * 8 + r;
                ulonglong2 gA = *(ulonglong2*)(Gx + b * 68 + jg * 4);
                gA.x = add2(gA.x, accA[r][0]); gA.y = add2(gA.y, accA[r][1]);
                *(ulonglong2*)(Gx + b * 68 + jg * 4) = gA;
                ulonglong2 gB = *(ulonglong2*)(Gx + b * 68 + 32 + jg * 4);
                gB.x = add2(gB.x, accB[r][0]); gB.y = add2(gB.y, accB[r][1]);
                *(ulonglong2*)(Gx + b * 68 + 32 + jg * 4) = gB;
            }
        }
        __syncthreads();

        // ---- LSTM cell update: thread = (hl, b-block of 8) ----
        {
            const int hl = tid & 15, bblk = tid >> 4;
            float* hout = hown + (size_t)t * H * B + (c * 16 + hl) * B;
#pragma unroll
            for (int u = 0; u < 8; ++u) {
                int b = bblk * 8 + u;
                float ig = Gx[b * 68 + hl];
                float fg = Gx[b * 68 + 16 + hl];
                float gg = Gx[b * 68 + 32 + hl];
                float og = Gx[b * 68 + 48 + hl];
                float cv = (t == 0) ? 0.f : cst[b * 16 + hl];
                float cn = sigm(fg) * cv + sigm(ig) * tanhfast(gg);
                cst[b * 16 + hl] = cn;
                hout[b] = sigm(og) * tanhfast(cn);
            }
        }
        __threadfence();
        __syncthreads();
        if (tid == 0) atomicAdd(&g_done[l * T + t], 1);
    }
}

// -------- final FC: out[b,t,v] = h7[t,:,b] . fc_w[v,:] + fc_b[v] --------
#define FC_SMEM_FLOATS (256 * 64 + 256 * 24 + 32)
__global__ void __launch_bounds__(256)
fc_kernel(const float* __restrict__ fcw, const float* __restrict__ fcb,
          float* __restrict__ out)
{
    extern __shared__ float fsm[];
    float* hs = fsm;                 // [k][b]
    float* ws = fsm + 256 * 64;      // [k][v] padded to 24
    float* bs = ws + 256 * 24;
    const int tid = threadIdx.x, t = blockIdx.x;

    const float* h7 = g_hseq + (size_t)(7 * T + t) * H * B;
    {
        const float4* s = (const float4*)h7;
        float4* d = (float4*)hs;
        for (int i = tid; i < 4096; i += 256) d[i] = s[i];
    }
    for (int i = tid; i < VOCAB * H; i += 256) {
        int v = i >> 8, k = i & 255;
        ws[k * 24 + v] = fcw[i];
    }
    if (tid < VOCAB) bs[tid] = fcb[tid];
    __syncthreads();

    const int b = tid & 63, vg = tid >> 6;
    const int v0 = vg * 6;
    const int nv = (v0 + 6 <= VOCAB) ? 6 : (VOCAB - v0);
    float acc[6] = {0.f, 0.f, 0.f, 0.f, 0.f, 0.f};
#pragma unroll 4
    for (int k = 0; k < 256; ++k) {
        float a = hs[k * 64 + b];
#pragma unroll
        for (int j = 0; j < 6; ++j) acc[j] += a * ws[k * 24 + v0 + j];
    }
    for (int j = 0; j < nv; ++j)
        out[((size_t)b * T + t) * VOCAB + v0 + j] = acc[j] + bs[v0 + j];
}

// -------- launch --------
extern "C" void kernel_launch(void* const* d_in, const int* in_sizes, int n_in,
                              void* d_out, int out_size)
{
    const int*   x        = (const int*)d_in[0];
    const float* emb      = (const float*)d_in[1];
    const float* Wih0     = (const float*)d_in[2];
    const float* Wih_rest = (const float*)d_in[3];
    const float* Whh      = (const float*)d_in[4];
    const float* bih      = (const float*)d_in[5];
    const float* bhh      = (const float*)d_in[6];
    const float* fcw      = (const float*)d_in[7];
    const float* fcb      = (const float*)d_in[8];
    float*       out      = (float*)d_out;

    cudaFuncSetAttribute(lstm_main_kernel,
                         cudaFuncAttributeMaxDynamicSharedMemorySize, SM_BYTES);
    cudaFuncSetAttribute(fc_kernel,
                         cudaFuncAttributeMaxDynamicSharedMemorySize, FC_SMEM_FLOATS * 4);

    zero_done_kernel<<<16, 256>>>();
    build_table_kernel<<<(VOCAB * G + 255) / 256, 256>>>(emb, Wih0, bih, bhh);
    lstm_main_kernel<<<LAYERS * NC, THR, SM_BYTES>>>(x, Wih_rest, Whh, bih, bhh);
    fc_kernel<<<T, 256, FC_SMEM_FLOATS * 4>>>(fcw, fcb, out);
}

// round 7
// speedup vs baseline: 1.4455x; 1.0562x over previous
#include <cuda_runtime.h>

#define LAYERS 8
#define T      512
#define B      64
#define H      256
#define G      1024        // 4H
#define VOCAB  23
#define EMB    16
#define NC     16          // CTAs per layer
#define JT     64          // gate rows per CTA
#define THR    256

typedef unsigned long long ull;

// -------- persistent device scratch --------
__device__ float g_hseq[(size_t)LAYERS * T * H * B];   // [l][t][k(H)][b]
__device__ float g_table[VOCAB * G];                   // fused layer-0 input+bias table
__device__ int   g_done[LAYERS * T];

// -------- helpers --------
__device__ __forceinline__ ull fma2(ull a, ull b, ull c) {
    ull d; asm("fma.rn.f32x2 %0, %1, %2, %3;" : "=l"(d) : "l"(a), "l"(b), "l"(c));
    return d;
}
__device__ __forceinline__ ull add2(ull a, ull b) {
    ull d; asm("add.rn.f32x2 %0, %1, %2;" : "=l"(d) : "l"(a), "l"(b));
    return d;
}
__device__ __forceinline__ ull pack2(float v) {
    ull d; asm("mov.b64 %0, {%1, %1};" : "=l"(d) : "f"(v));
    return d;
}
__device__ __forceinline__ float tanha(float x) {
    float y; asm("tanh.approx.f32 %0, %1;" : "=f"(y) : "f"(x));
    return y;
}
__device__ __forceinline__ float sigm(float x) {
    return fmaf(0.5f, tanha(0.5f * x), 0.5f);
}

__device__ __forceinline__ void wait_done(int idx) {
    if (threadIdx.x == 0) {
        volatile int* p = &g_done[idx];
        while (*p < NC) __nanosleep(32);
    }
    __syncthreads();
}

// -------- smem layout (floats) --------
#define SM_WHH   0
#define SM_WIH   16384
#define SM_AST   32768                 // [2 kg][2 buf][32 k][64 b] = 8192
#define SM_GX    40960                 // [64 b][68]; col = hl*4 + gate
#define SM_CST   45312                 // [16 hl][64 b]
#define SM_BIAS  46336                 // 64
#define SM_TOK   46400                 // 64 ints
#define SM_FLOATS 46464
#define SM_BYTES  (SM_FLOATS * 4)

// j-local -> global gate row permutation: jl = hl*4 + gate (hl = jl>>2, gate = jl&3)
__device__ __forceinline__ int jmap(int jl, int c) {
    return (jl & 3) * H + c * 16 + (jl >> 2);
}

// -------- prelude kernels --------
__global__ void zero_done_kernel() {
    int i = blockIdx.x * blockDim.x + threadIdx.x;
    if (i < LAYERS * T) g_done[i] = 0;
}

__global__ void build_table_kernel(const float* __restrict__ emb,
                                   const float* __restrict__ Wih0,
                                   const float* __restrict__ bih,
                                   const float* __restrict__ bhh) {
    int idx = blockIdx.x * blockDim.x + threadIdx.x;
    if (idx >= VOCAB * G) return;
    int v = idx / G, j = idx % G;
    float s = bih[j] + bhh[j];
#pragma unroll
    for (int e = 0; e < EMB; ++e) s += emb[v * EMB + e] * Wih0[j * EMB + e];
    g_table[idx] = s;
}

// One K-half GEMM pass: acc += A[khalf,b] * W[khalf,j], thread tile 4b x 8j.
// 128 threads per k-group; A staged to smem in 32-k double-buffered chunks.
__device__ __forceinline__ void gemm_half(
    const float* __restrict__ Aglob, const float* __restrict__ Ws,
    float* __restrict__ AstAll,
    ull (&accA)[4][2], ull (&accB)[4][2],
    int kg, int jg, int bgrp, int ltid)
{
    const float* src = Aglob + kg * (128 * 64);
    float* base = AstAll + kg * 4096;

    // stage chunk 0
    {
        const float4* s = (const float4*)src;
        float4* d = (float4*)base;
#pragma unroll
        for (int u = 0; u < 4; ++u) d[ltid + u * 128] = s[ltid + u * 128];
    }
    __syncthreads();

#pragma unroll 1
    for (int r = 0; r < 4; ++r) {
        float4 pf0, pf1, pf2, pf3;
        if (r < 3) {
            const float4* s = (const float4*)(src + (r + 1) * 2048);
            pf0 = s[ltid];        pf1 = s[ltid + 128];
            pf2 = s[ltid + 256];  pf3 = s[ltid + 384];
        }
        const float* Ab = base + (r & 1) * 2048;
        const float* Wk = Ws + (kg * 128 + r * 32) * 64;
#pragma unroll 4
        for (int k = 0; k < 32; ++k) {
            ulonglong2 wA = *(const ulonglong2*)(Wk + k * 64 + jg * 4);
            ulonglong2 wB = *(const ulonglong2*)(Wk + k * 64 + 32 + jg * 4);
            float4 a = *(const float4*)(Ab + k * 64 + bgrp * 4);
#define ROWF(rr, av) { ull p = pack2(av); \
            accA[rr][0] = fma2(p, wA.x, accA[rr][0]); \
            accA[rr][1] = fma2(p, wA.y, accA[rr][1]); \
            accB[rr][0] = fma2(p, wB.x, accB[rr][0]); \
            accB[rr][1] = fma2(p, wB.y, accB[rr][1]); }
            ROWF(0, a.x) ROWF(1, a.y) ROWF(2, a.z) ROWF(3, a.w)
#undef ROWF
        }
        if (r < 3) {
            float4* d = (float4*)(base + ((r + 1) & 1) * 2048);
            d[ltid]       = pf0;  d[ltid + 128] = pf1;
            d[ltid + 256] = pf2;  d[ltid + 384] = pf3;
        }
        __syncthreads();
    }
}

// -------- main persistent wavefront kernel --------
extern "C" __global__ void __launch_bounds__(THR, 1)
lstm_main_kernel(const int* __restrict__ x,
                 const float* __restrict__ Wih_rest,
                 const float* __restrict__ Whh,
                 const float* __restrict__ bih,
                 const float* __restrict__ bhh)
{
    extern __shared__ float smem[];
    const int tid  = threadIdx.x;
    const int l    = blockIdx.x / NC;
    const int c    = blockIdx.x % NC;
    const int kg   = tid >> 7;        // k-half 0/1 (4 warps each)
    const int ltid = tid & 127;
    const int jg   = ltid & 7;        // j in {4jg..4jg+3} U {32+4jg..+3}
    const int bgrp = ltid >> 3;       // 0..15 -> b = 4*bgrp..+3

    float* WhhS  = smem + SM_WHH;
    float* WihS  = smem + SM_WIH;     // l==0: token table slice [VOCAB][64]
    float* Ast   = smem + SM_AST;
    float* Gx    = smem + SM_GX;      // [64][68], col = hl*4+gate
    float* cst   = smem + SM_CST;     // [16][64]
    float* biasS = smem + SM_BIAS;
    int*   tokI  = (int*)(smem + SM_TOK);
    float* tabS  = WihS;

    // ---- resident weights (transposed [k][jl], jl gate-interleaved) ----
    {
        const float* Wl = Whh + (size_t)l * G * H;
        for (int idx = tid; idx < H * JT; idx += THR) {
            int k = idx >> 6, jl = idx & 63;
            WhhS[idx] = Wl[(size_t)jmap(jl, c) * H + k];
        }
    }
    if (l == 0) {
        for (int idx = tid; idx < VOCAB * JT; idx += THR) {
            int v = idx / JT, jl = idx % JT;
            tabS[idx] = g_table[v * G + jmap(jl, c)];
        }
    } else {
        const float* Wl = Wih_rest + (size_t)(l - 1) * G * H;
        for (int idx = tid; idx < H * JT; idx += THR) {
            int k = idx >> 6, jl = idx & 63;
            WihS[idx] = Wl[(size_t)jmap(jl, c) * H + k];
        }
        if (tid < JT) {
            int jgl = jmap(tid, c);
            biasS[tid] = bih[l * G + jgl] + bhh[l * G + jgl];
        }
    }
    __syncthreads();

    float*       hown = g_hseq + (size_t)l * T * H * B;
    const float* hin  = (l > 0) ? (g_hseq + (size_t)(l - 1) * T * H * B) : (const float*)0;

    for (int t = 0; t < T; ++t) {
        ull accA[4][2], accB[4][2];

        // ---- accumulator init ----
        if (l == 0) {
            if (tid < 64) tokI[tid] = x[tid * T + t];
            __syncthreads();
            if (kg == 0) {
#pragma unroll
                for (int r = 0; r < 4; ++r) {
                    int tk = tokI[bgrp * 4 + r];
                    ulonglong2 pA = *(const ulonglong2*)(tabS + tk * 64 + jg * 4);
                    ulonglong2 pB = *(const ulonglong2*)(tabS + tk * 64 + 32 + jg * 4);
                    accA[r][0] = pA.x; accA[r][1] = pA.y;
                    accB[r][0] = pB.x; accB[r][1] = pB.y;
                }
            } else {
#pragma unroll
                for (int r = 0; r < 4; ++r) { accA[r][0]=accA[r][1]=accB[r][0]=accB[r][1]=0ULL; }
            }
        } else {
            if (kg == 0) {
                ulonglong2 pA = *(const ulonglong2*)(biasS + jg * 4);
                ulonglong2 pB = *(const ulonglong2*)(biasS + 32 + jg * 4);
#pragma unroll
                for (int r = 0; r < 4; ++r) {
                    accA[r][0] = pA.x; accA[r][1] = pA.y;
                    accB[r][0] = pB.x; accB[r][1] = pB.y;
                }
            } else {
#pragma unroll
                for (int r = 0; r < 4; ++r) { accA[r][0]=accA[r][1]=accB[r][0]=accB[r][1]=0ULL; }
            }
        }

        // ---- recurrent pass, then input pass ----
        if (t > 0) {
            wait_done(l * T + (t - 1));
            gemm_half(hown + (size_t)(t - 1) * H * B, WhhS, Ast, accA, accB, kg, jg, bgrp, ltid);
        }
        if (l > 0) {
            wait_done((l - 1) * T + t);
            gemm_half(hin + (size_t)t * H * B, WihS, Ast, accA, accB, kg, jg, bgrp, ltid);
        }

        // ---- split-K reduction into Gx ----
        if (kg == 0) {
#pragma unroll
            for (int r = 0; r < 4; ++r) {
                int b = bgrp * 4 + r;
                *(ulonglong2*)(Gx + b * 68 + jg * 4)      = make_ulonglong2(accA[r][0], accA[r][1]);
                *(ulonglong2*)(Gx + b * 68 + 32 + jg * 4) = make_ulonglong2(accB[r][0], accB[r][1]);
            }
        }
        __syncthreads();
        if (kg == 1) {
#pragma unroll
            for (int r = 0; r < 4; ++r) {
                int b = bgrp * 4 + r;
                ulonglong2 gA = *(ulonglong2*)(Gx + b * 68 + jg * 4);
                gA.x = add2(gA.x, accA[r][0]); gA.y = add2(gA.y, accA[r][1]);
                *(ulonglong2*)(Gx + b * 68 + jg * 4) = gA;
                ulonglong2 gB = *(ulonglong2*)(Gx + b * 68 + 32 + jg * 4);
                gB.x = add2(gB.x, accB[r][0]); gB.y = add2(gB.y, accB[r][1]);
                *(ulonglong2*)(Gx + b * 68 + 32 + jg * 4) = gB;
            }
        }
        __syncthreads();

        // ---- LSTM cell update: thread = (b, 4 consecutive hl); coalesced h store ----
        {
            const int b = tid & 63, hlg = tid >> 6;
            float* hout = hown + (size_t)t * H * B;
#pragma unroll
            for (int i = 0; i < 4; ++i) {
                int hl = hlg * 4 + i;
                float4 g = *(const float4*)(Gx + b * 68 + hl * 4);  // i,f,g,o
                float cv = (t == 0) ? 0.f : cst[hl * 64 + b];
                float cn = sigm(g.y) * cv + sigm(g.x) * tanha(g.z);
                cst[hl * 64 + b] = cn;
                hout[(c * 16 + hl) * B + b] = sigm(g.w) * tanha(cn);
            }
        }
        __threadfence();
        __syncthreads();
        if (tid == 0) atomicAdd(&g_done[l * T + t], 1);
    }
}

// -------- final FC: out[b,t,v] = h7[t,:,b] . fc_w[v,:] + fc_b[v] --------
#define FC_SMEM_FLOATS (256 * 64 + 256 * 24 + 32)
__global__ void __launch_bounds__(256)
fc_kernel(const float* __restrict__ fcw, const float* __restrict__ fcb,
          float* __restrict__ out)
{
    extern __shared__ float fsm[];
    float* hs = fsm;                 // [k][b]
    float* ws = fsm + 256 * 64;      // [k][v] padded to 24
    float* bs = ws + 256 * 24;
    const int tid = threadIdx.x, t = blockIdx.x;

    const float* h7 = g_hseq + (size_t)(7 * T + t) * H * B;
    {
        const float4* s = (const float4*)h7;
        float4* d = (float4*)hs;
        for (int i = tid; i < 4096; i += 256) d[i] = s[i];
    }
    for (int i = tid; i < VOCAB * H; i += 256) {
        int v = i >> 8, k = i & 255;
        ws[k * 24 + v] = fcw[i];
    }
    if (tid < VOCAB) bs[tid] = fcb[tid];
    __syncthreads();

    const int b = tid & 63, vg = tid >> 6;
    const int v0 = vg * 6;
    const int nv = (v0 + 6 <= VOCAB) ? 6 : (VOCAB - v0);
    float acc[6] = {0.f, 0.f, 0.f, 0.f, 0.f, 0.f};
#pragma unroll 4
    for (int k = 0; k < 256; ++k) {
        float a = hs[k * 64 + b];
#pragma unroll
        for (int j = 0; j < 6; ++j) acc[j] += a * ws[k * 24 + v0 + j];
    }
    for (int j = 0; j < nv; ++j)
        out[((size_t)b * T + t) * VOCAB + v0 + j] = acc[j] + bs[v0 + j];
}

// -------- launch --------
extern "C" void kernel_launch(void* const* d_in, const int* in_sizes, int n_in,
                              void* d_out, int out_size)
{
    const int*   x        = (const int*)d_in[0];
    const float* emb      = (const float*)d_in[1];
    const float* Wih0     = (const float*)d_in[2];
    const float* Wih_rest = (const float*)d_in[3];
    const float* Whh      = (const float*)d_in[4];
    const float* bih      = (const float*)d_in[5];
    const float* bhh      = (const float*)d_in[6];
    const float* fcw      = (const float*)d_in[7];
    const float* fcb      = (const float*)d_in[8];
    float*       out      = (float*)d_out;

    cudaFuncSetAttribute(lstm_main_kernel,
                         cudaFuncAttributeMaxDynamicSharedMemorySize, SM_BYTES);
    cudaFuncSetAttribute(fc_kernel,
                         cudaFuncAttributeMaxDynamicSharedMemorySize, FC_SMEM_FLOATS * 4);

    zero_done_kernel<<<16, 256>>>();
    build_table_kernel<<<(VOCAB * G + 255) / 256, 256>>>(emb, Wih0, bih, bhh);
    lstm_main_kernel<<<LAYERS * NC, THR, SM_BYTES>>>(x, Wih_rest, Whh, bih, bhh);
    fc_kernel<<<T, 256, FC_SMEM_FLOATS * 4>>>(fcw, fcb, out);
}

// round 8
// speedup vs baseline: 1.4455x; 1.0000x over previous
#include <cuda_runtime.h>

#define LAYERS 8
#define T      512
#define B      64
#define H      256
#define G      1024        // 4H
#define VOCAB  23
#define EMB    16
#define NC     16          // CTAs per layer
#define JT     64          // gate rows per CTA
#define THR    256

typedef unsigned long long ull;

// -------- persistent device scratch --------
__device__ float g_hseq[(size_t)LAYERS * T * H * B];   // [l][t][k(H)][b]
__device__ float g_table[VOCAB * G];                   // fused layer-0 input+bias table
__device__ int   g_done[LAYERS * T];

// -------- helpers --------
__device__ __forceinline__ ull fma2(ull a, ull b, ull c) {
    ull d; asm("fma.rn.f32x2 %0, %1, %2, %3;" : "=l"(d) : "l"(a), "l"(b), "l"(c));
    return d;
}
__device__ __forceinline__ ull add2(ull a, ull b) {
    ull d; asm("add.rn.f32x2 %0, %1, %2;" : "=l"(d) : "l"(a), "l"(b));
    return d;
}
__device__ __forceinline__ ull pack2(float v) {
    ull d; asm("mov.b64 %0, {%1, %1};" : "=l"(d) : "f"(v));
    return d;
}
__device__ __forceinline__ float tanha(float x) {
    float y; asm("tanh.approx.f32 %0, %1;" : "=f"(y) : "f"(x));
    return y;
}
__device__ __forceinline__ float sigm(float x) {
    return fmaf(0.5f, tanha(0.5f * x), 0.5f);
}

__device__ __forceinline__ void wait_done(int idx) {
    if (threadIdx.x == 0) {
        volatile int* p = &g_done[idx];
        while (*p < NC) __nanosleep(32);
    }
    __syncthreads();
}

// -------- smem layout (floats) --------
#define SM_WHH   0
#define SM_WIH   16384
#define SM_AST   32768                 // [2 kg][2 buf][32 k][64 b] = 8192
#define SM_GX    40960                 // [64 b][68]; col = hl*4 + gate
#define SM_CST   45312                 // [16 hl][64 b]
#define SM_BIAS  46336                 // 64
#define SM_TOK   46400                 // 64 ints
#define SM_FLOATS 46464
#define SM_BYTES  (SM_FLOATS * 4)

// j-local -> global gate row permutation: jl = hl*4 + gate (hl = jl>>2, gate = jl&3)
__device__ __forceinline__ int jmap(int jl, int c) {
    return (jl & 3) * H + c * 16 + (jl >> 2);
}

// -------- prelude kernels --------
__global__ void zero_done_kernel() {
    int i = blockIdx.x * blockDim.x + threadIdx.x;
    if (i < LAYERS * T) g_done[i] = 0;
}

__global__ void build_table_kernel(const float* __restrict__ emb,
                                   const float* __restrict__ Wih0,
                                   const float* __restrict__ bih,
                                   const float* __restrict__ bhh) {
    int idx = blockIdx.x * blockDim.x + threadIdx.x;
    if (idx >= VOCAB * G) return;
    int v = idx / G, j = idx % G;
    float s = bih[j] + bhh[j];
#pragma unroll
    for (int e = 0; e < EMB; ++e) s += emb[v * EMB + e] * Wih0[j * EMB + e];
    g_table[idx] = s;
}

// One K-half GEMM pass: acc += A[khalf,b] * W[khalf,j], thread tile 4b x 8j.
// 128 threads per k-group; A staged to smem in 32-k double-buffered chunks.
__device__ __forceinline__ void gemm_half(
    const float* __restrict__ Aglob, const float* __restrict__ Ws,
    float* __restrict__ AstAll,
    ull (&accA)[4][2], ull (&accB)[4][2],
    int kg, int jg, int bgrp, int ltid)
{
    const float* src = Aglob + kg * (128 * 64);
    float* base = AstAll + kg * 4096;

    // stage chunk 0
    {
        const float4* s = (const float4*)src;
        float4* d = (float4*)base;
#pragma unroll
        for (int u = 0; u < 4; ++u) d[ltid + u * 128] = s[ltid + u * 128];
    }
    __syncthreads();

#pragma unroll 1
    for (int r = 0; r < 4; ++r) {
        float4 pf0, pf1, pf2, pf3;
        if (r < 3) {
            const float4* s = (const float4*)(src + (r + 1) * 2048);
            pf0 = s[ltid];        pf1 = s[ltid + 128];
            pf2 = s[ltid + 256];  pf3 = s[ltid + 384];
        }
        const float* Ab = base + (r & 1) * 2048;
        const float* Wk = Ws + (kg * 128 + r * 32) * 64;
#pragma unroll 4
        for (int k = 0; k < 32; ++k) {
            ulonglong2 wA = *(const ulonglong2*)(Wk + k * 64 + jg * 4);
            ulonglong2 wB = *(const ulonglong2*)(Wk + k * 64 + 32 + jg * 4);
            float4 a = *(const float4*)(Ab + k * 64 + bgrp * 4);
#define ROWF(rr, av) { ull p = pack2(av); \
            accA[rr][0] = fma2(p, wA.x, accA[rr][0]); \
            accA[rr][1] = fma2(p, wA.y, accA[rr][1]); \
            accB[rr][0] = fma2(p, wB.x, accB[rr][0]); \
            accB[rr][1] = fma2(p, wB.y, accB[rr][1]); }
            ROWF(0, a.x) ROWF(1, a.y) ROWF(2, a.z) ROWF(3, a.w)
#undef ROWF
        }
        if (r < 3) {
            float4* d = (float4*)(base + ((r + 1) & 1) * 2048);
            d[ltid]       = pf0;  d[ltid + 128] = pf1;
            d[ltid + 256] = pf2;  d[ltid + 384] = pf3;
        }
        __syncthreads();
    }
}

// -------- main persistent wavefront kernel --------
extern "C" __global__ void __launch_bounds__(THR, 1)
lstm_main_kernel(const int* __restrict__ x,
                 const float* __restrict__ Wih_rest,
                 const float* __restrict__ Whh,
                 const float* __restrict__ bih,
                 const float* __restrict__ bhh)
{
    extern __shared__ float smem[];
    const int tid  = threadIdx.x;
    const int l    = blockIdx.x / NC;
    const int c    = blockIdx.x % NC;
    const int kg   = tid >> 7;        // k-half 0/1 (4 warps each)
    const int ltid = tid & 127;
    const int jg   = ltid & 7;        // j in {4jg..4jg+3} U {32+4jg..+3}
    const int bgrp = ltid >> 3;       // 0..15 -> b = 4*bgrp..+3

    float* WhhS  = smem + SM_WHH;
    float* WihS  = smem + SM_WIH;     // l==0: token table slice [VOCAB][64]
    float* Ast   = smem + SM_AST;
    float* Gx    = smem + SM_GX;      // [64][68], col = hl*4+gate
    float* cst   = smem + SM_CST;     // [16][64]
    float* biasS = smem + SM_BIAS;
    int*   tokI  = (int*)(smem + SM_TOK);
    float* tabS  = WihS;

    // ---- resident weights (transposed [k][jl], jl gate-interleaved) ----
    {
        const float* Wl = Whh + (size_t)l * G * H;
        for (int idx = tid; idx < H * JT; idx += THR) {
            int k = idx >> 6, jl = idx & 63;
            WhhS[idx] = Wl[(size_t)jmap(jl, c) * H + k];
        }
    }
    if (l == 0) {
        for (int idx = tid; idx < VOCAB * JT; idx += THR) {
            int v = idx / JT, jl = idx % JT;
            tabS[idx] = g_table[v * G + jmap(jl, c)];
        }
    } else {
        const float* Wl = Wih_rest + (size_t)(l - 1) * G * H;
        for (int idx = tid; idx < H * JT; idx += THR) {
            int k = idx >> 6, jl = idx & 63;
            WihS[idx] = Wl[(size_t)jmap(jl, c) * H + k];
        }
        if (tid < JT) {
            int jgl = jmap(tid, c);
            biasS[tid] = bih[l * G + jgl] + bhh[l * G + jgl];
        }
    }
    __syncthreads();

    float*       hown = g_hseq + (size_t)l * T * H * B;
    const float* hin  = (l > 0) ? (g_hseq + (size_t)(l - 1) * T * H * B) : (const float*)0;

    for (int t = 0; t < T; ++t) {
        ull accA[4][2], accB[4][2];

        // ---- accumulator init ----
        if (l == 0) {
            if (tid < 64) tokI[tid] = x[tid * T + t];
            __syncthreads();
            if (kg == 0) {
#pragma unroll
                for (int r = 0; r < 4; ++r) {
                    int tk = tokI[bgrp * 4 + r];
                    ulonglong2 pA = *(const ulonglong2*)(tabS + tk * 64 + jg * 4);
                    ulonglong2 pB = *(const ulonglong2*)(tabS + tk * 64 + 32 + jg * 4);
                    accA[r][0] = pA.x; accA[r][1] = pA.y;
                    accB[r][0] = pB.x; accB[r][1] = pB.y;
                }
            } else {
#pragma unroll
                for (int r = 0; r < 4; ++r) { accA[r][0]=accA[r][1]=accB[r][0]=accB[r][1]=0ULL; }
            }
        } else {
            if (kg == 0) {
                ulonglong2 pA = *(const ulonglong2*)(biasS + jg * 4);
                ulonglong2 pB = *(const ulonglong2*)(biasS + 32 + jg * 4);
#pragma unroll
                for (int r = 0; r < 4; ++r) {
                    accA[r][0] = pA.x; accA[r][1] = pA.y;
                    accB[r][0] = pB.x; accB[r][1] = pB.y;
                }
            } else {
#pragma unroll
                for (int r = 0; r < 4; ++r) { accA[r][0]=accA[r][1]=accB[r][0]=accB[r][1]=0ULL; }
            }
        }

        // ---- recurrent pass, then input pass ----
        if (t > 0) {
            wait_done(l * T + (t - 1));
            gemm_half(hown + (size_t)(t - 1) * H * B, WhhS, Ast, accA, accB, kg, jg, bgrp, ltid);
        }
        if (l > 0) {
            wait_done((l - 1) * T + t);
            gemm_half(hin + (size_t)t * H * B, WihS, Ast, accA, accB, kg, jg, bgrp, ltid);
        }

        // ---- split-K reduction into Gx ----
        if (kg == 0) {
#pragma unroll
            for (int r = 0; r < 4; ++r) {
                int b = bgrp * 4 + r;
                *(ulonglong2*)(Gx + b * 68 + jg * 4)      = make_ulonglong2(accA[r][0], accA[r][1]);
                *(ulonglong2*)(Gx + b * 68 + 32 + jg * 4) = make_ulonglong2(accB[r][0], accB[r][1]);
            }
        }
        __syncthreads();
        if (kg == 1) {
#pragma unroll
            for (int r = 0; r < 4; ++r) {
                int b = bgrp * 4 + r;
                ulonglong2 gA = *(ulonglong2*)(Gx + b * 68 + jg * 4);
                gA.x = add2(gA.x, accA[r][0]); gA.y = add2(gA.y, accA[r][1]);
                *(ulonglong2*)(Gx + b * 68 + jg * 4) = gA;
                ulonglong2 gB = *(ulonglong2*)(Gx + b * 68 + 32 + jg * 4);
                gB.x = add2(gB.x, accB[r][0]); gB.y = add2(gB.y, accB[r][1]);
                *(ulonglong2*)(Gx + b * 68 + 32 + jg * 4) = gB;
            }
        }
        __syncthreads();

        // ---- LSTM cell update: thread = (b, 4 consecutive hl); coalesced h store ----
        {
            const int b = tid & 63, hlg = tid >> 6;
            float* hout = hown + (size_t)t * H * B;
#pragma unroll
            for (int i = 0; i < 4; ++i) {
                int hl = hlg * 4 + i;
                float4 g = *(const float4*)(Gx + b * 68 + hl * 4);  // i,f,g,o
                float cv = (t == 0) ? 0.f : cst[hl * 64 + b];
                float cn = sigm(g.y) * cv + sigm(g.x) * tanha(g.z);
                cst[hl * 64 + b] = cn;
                hout[(c * 16 + hl) * B + b] = sigm(g.w) * tanha(cn);
            }
        }
        __threadfence();
        __syncthreads();
        if (tid == 0) atomicAdd(&g_done[l * T + t], 1);
    }
}

// -------- final FC: out[b,t,v] = h7[t,:,b] . fc_w[v,:] + fc_b[v] --------
#define FC_SMEM_FLOATS (256 * 64 + 256 * 24 + 32)
__global__ void __launch_bounds__(256)
fc_kernel(const float* __restrict__ fcw, const float* __restrict__ fcb,
          float* __restrict__ out)
{
    extern __shared__ float fsm[];
    float* hs = fsm;                 // [k][b]
    float* ws = fsm + 256 * 64;      // [k][v] padded to 24
    float* bs = ws + 256 * 24;
    const int tid = threadIdx.x, t = blockIdx.x;

    const float* h7 = g_hseq + (size_t)(7 * T + t) * H * B;
    {
        const float4* s = (const float4*)h7;
        float4* d = (float4*)hs;
        for (int i = tid; i < 4096; i += 256) d[i] = s[i];
    }
    for (int i = tid; i < VOCAB * H; i += 256) {
        int v = i >> 8, k = i & 255;
        ws[k * 24 + v] = fcw[i];
    }
    if (tid < VOCAB) bs[tid] = fcb[tid];
    __syncthreads();

    const int b = tid & 63, vg = tid >> 6;
    const int v0 = vg * 6;
    const int nv = (v0 + 6 <= VOCAB) ? 6 : (VOCAB - v0);
    float acc[6] = {0.f, 0.f, 0.f, 0.f, 0.f, 0.f};
#pragma unroll 4
    for (int k = 0; k < 256; ++k) {
        float a = hs[k * 64 + b];
#pragma unroll
        for (int j = 0; j < 6; ++j) acc[j] += a * ws[k * 24 + v0 + j];
    }
    for (int j = 0; j < nv; ++j)
        out[((size_t)b * T + t) * VOCAB + v0 + j] = acc[j] + bs[v0 + j];
}

// -------- launch --------
extern "C" void kernel_launch(void* const* d_in, const int* in_sizes, int n_in,
                              void* d_out, int out_size)
{
    const int*   x        = (const int*)d_in[0];
    const float* emb      = (const float*)d_in[1];
    const float* Wih0     = (const float*)d_in[2];
    const float* Wih_rest = (const float*)d_in[3];
    const float* Whh      = (const float*)d_in[4];
    const float* bih      = (const float*)d_in[5];
    const float* bhh      = (const float*)d_in[6];
    const float* fcw      = (const float*)d_in[7];
    const float* fcb      = (const float*)d_in[8];
    float*       out      = (float*)d_out;

    cudaFuncSetAttribute(lstm_main_kernel,
                         cudaFuncAttributeMaxDynamicSharedMemorySize, SM_BYTES);
    cudaFuncSetAttribute(fc_kernel,
                         cudaFuncAttributeMaxDynamicSharedMemorySize, FC_SMEM_FLOATS * 4);

    zero_done_kernel<<<16, 256>>>();
    build_table_kernel<<<(VOCAB * G + 255) / 256, 256>>>(emb, Wih0, bih, bhh);
    lstm_main_kernel<<<LAYERS * NC, THR, SM_BYTES>>>(x, Wih_rest, Whh, bih, bhh);
    fc_kernel<<<T, 256, FC_SMEM_FLOATS * 4>>>(fcw, fcb, out);
}

// round 10
// speedup vs baseline: 2.5365x; 1.7548x over previous
#include <cuda_runtime.h>
#include <cuda_bf16.h>
#include <cstdint>

#define LAYERS 8
#define T      512
#define B      64
#define H      256
#define G      1024
#define VOCAB  23
#define EMB    16
#define NC     16
#define THR    256

#define WSTR   528            // bytes per padded row (264 bf16)
#define PLANE  33792          // 64 rows * 528

// smem byte offsets
#define SB_WHH_HI 0
#define SB_WHH_LO 33792
#define SB_WIH_HI 67584
#define SB_WIH_LO 101376
#define SB_BST    135168      // staged h: hi plane, lo plane at +PLANE
#define SB_GX     135168      // alias over staging: f32 [64][68]
#define SB_CST    202752      // f32 [16][68]
#define SB_TAB    207104      // float4 [23*16]
#define SB_BIAS   212992      // float4 [16]
#define SB_TOK    213248      // int [64]
#define SMEM_BYTES 213504

static __device__ __align__(128) __nv_bfloat16 g_hbf[(size_t)LAYERS * T * 2 * 16384];
static __device__ float g_hseq7[(size_t)T * H * B];
static __device__ float g_table[VOCAB * G];
static __device__ int   g_done[LAYERS * T];

// ---------- helpers ----------
__device__ __forceinline__ uint32_t smem_u32(const void* p) {
    uint32_t a;
    asm("{ .reg .u64 t; cvta.to.shared.u64 t, %1; cvt.u32.u64 %0, t; }" : "=r"(a) : "l"(p));
    return a;
}
__device__ __forceinline__ float tanha(float x) {
    float y; asm("tanh.approx.f32 %0, %1;" : "=f"(y) : "f"(x));
    return y;
}
__device__ __forceinline__ float sigm(float x) { return fmaf(0.5f, tanha(0.5f * x), 0.5f); }

__device__ __forceinline__ void wait_done(int idx) {
    if (threadIdx.x == 0) {
        volatile int* p = &g_done[idx];
        while (*p < NC) __nanosleep(32);
    }
    __syncthreads();
}

#define LDSM4(r0,r1,r2,r3,addr) \
    asm volatile("ldmatrix.sync.aligned.m8n8.x4.shared.b16 {%0,%1,%2,%3}, [%4];" \
                 : "=r"(r0),"=r"(r1),"=r"(r2),"=r"(r3) : "r"(addr))

#define MMA16816(c, a0,a1,a2,a3, b0,b1) \
    asm volatile("mma.sync.aligned.m16n8k16.row.col.f32.bf16.bf16.f32 " \
                 "{%0,%1,%2,%3},{%4,%5,%6,%7},{%8,%9},{%0,%1,%2,%3};" \
                 : "+f"((c)[0]),"+f"((c)[1]),"+f"((c)[2]),"+f"((c)[3]) \
                 : "r"(a0),"r"(a1),"r"(a2),"r"(a3),"r"(b0),"r"(b1))

// One split-precision term: acc += A[32x128] * B[32x128]^T slice for this warp.
// A rows: mi*32 + (0..31); B rows (n): ni*32 + (0..31); k range kh*128..+127.
__device__ __forceinline__ void gemm_term(
    uint32_t aPlane, uint32_t bPlane, float (&acc)[2][4][4],
    int mi, int ni, int kh, int lane)
{
    const uint32_t kOff = (uint32_t)(kh * 256) + ((lane >> 4) << 4);  // kh*128 elems *2B + quad 16B
    uint32_t aRow = aPlane + (uint32_t)(mi * 32 + (lane & 15)) * WSTR + kOff;
    uint32_t bRow = bPlane + (uint32_t)(ni * 32 + (lane & 15)) * WSTR + kOff;
#pragma unroll
    for (int k16 = 0; k16 < 8; ++k16) {
        uint32_t a0,a1,a2,a3, a4,a5,a6,a7;
        uint32_t b0,b1,b2,b3, b4,b5,b6,b7;
        LDSM4(a0,a1,a2,a3, aRow + k16 * 32);
        LDSM4(a4,a5,a6,a7, aRow + 16 * WSTR + k16 * 32);
        LDSM4(b0,b1,b2,b3, bRow + k16 * 32);
        LDSM4(b4,b5,b6,b7, bRow + 16 * WSTR + k16 * 32);
        MMA16816(acc[0][0], a0,a1,a2,a3, b0,b2);
        MMA16816(acc[0][1], a0,a1,a2,a3, b1,b3);
        MMA16816(acc[0][2], a0,a1,a2,a3, b4,b6);
        MMA16816(acc[0][3], a0,a1,a2,a3, b5,b7);
        MMA16816(acc[1][0], a4,a5,a6,a7, b0,b2);
        MMA16816(acc[1][1], a4,a5,a6,a7, b1,b3);
        MMA16816(acc[1][2], a4,a5,a6,a7, b4,b6);
        MMA16816(acc[1][3], a4,a5,a6,a7, b5,b7);
    }
}

// copy one dense 32KB global plane into padded smem plane
__device__ __forceinline__ void copy_plane(char* dstS, const char* src, int tid) {
#pragma unroll
    for (int i = tid; i < 2048; i += THR) {
        int b = i >> 5, kc = i & 31;
        *(uint4*)(dstS + b * WSTR + kc * 16) = *(const uint4*)(src + b * 512 + kc * 16);
    }
}

// ---------- prelude ----------
__global__ void zero_done_kernel() {
    int i = blockIdx.x * blockDim.x + threadIdx.x;
    if (i < LAYERS * T) g_done[i] = 0;
}
__global__ void build_table_kernel(const float* __restrict__ emb, const float* __restrict__ Wih0,
                                   const float* __restrict__ bih, const float* __restrict__ bhh) {
    int idx = blockIdx.x * blockDim.x + threadIdx.x;
    if (idx >= VOCAB * G) return;
    int v = idx / G, j = idx % G;
    float s = bih[j] + bhh[j];
#pragma unroll
    for (int e = 0; e < EMB; ++e) s += emb[v * EMB + e] * Wih0[j * EMB + e];
    g_table[idx] = s;
}

// ---------- main persistent wavefront kernel ----------
extern "C" __global__ void __launch_bounds__(THR, 1)
lstm_main_kernel(const int* __restrict__ x,
                 const float* __restrict__ Wih_rest,
                 const float* __restrict__ Whh,
                 const float* __restrict__ bih,
                 const float* __restrict__ bhh)
{
    extern __shared__ char smem[];
    const uint32_t sb = smem_u32(smem);
    const int tid  = threadIdx.x;
    const int warp = tid >> 5, lane = tid & 31;
    const int l = blockIdx.x >> 4;
    const int c = blockIdx.x & 15;          // unit block: units c*16 .. c*16+15
    const int kh = warp >> 2, mi = (warp >> 1) & 1, ni = warp & 1;

    float*  gx    = (float*)(smem + SB_GX);     // [64][68]
    float*  cst   = (float*)(smem + SB_CST);    // [16][68]
    float4* tab4  = (float4*)(smem + SB_TAB);
    float4* bias4 = (float4*)(smem + SB_BIAS);
    int*    tokI  = (int*)(smem + SB_TOK);

    // ---- resident weights: bf16 hi/lo planes, rows r = gate*16 + u, padded ----
    {
        const float* Wl = Whh + (size_t)l * G * H;
        for (int idx = tid; idx < 64 * 256; idx += THR) {
            int r = idx >> 8, k = idx & 255;
            int jg = (r >> 4) * H + c * 16 + (r & 15);
            float w = Wl[(size_t)jg * H + k];
            __nv_bfloat16 wh = __float2bfloat16(w);
            *(__nv_bfloat16*)(smem + SB_WHH_HI + r * WSTR + k * 2) = wh;
            *(__nv_bfloat16*)(smem + SB_WHH_LO + r * WSTR + k * 2) =
                __float2bfloat16(w - __bfloat162float(wh));
        }
    }
    if (l > 0) {
        const float* Wl = Wih_rest + (size_t)(l - 1) * G * H;
        for (int idx = tid; idx < 64 * 256; idx += THR) {
            int r = idx >> 8, k = idx & 255;
            int jg = (r >> 4) * H + c * 16 + (r & 15);
            float w = Wl[(size_t)jg * H + k];
            __nv_bfloat16 wh = __float2bfloat16(w);
            *(__nv_bfloat16*)(smem + SB_WIH_HI + r * WSTR + k * 2) = wh;
            *(__nv_bfloat16*)(smem + SB_WIH_LO + r * WSTR + k * 2) =
                __float2bfloat16(w - __bfloat162float(wh));
        }
        if (tid < 16) {
            int u = tid;
            float4 q;
            q.x = bih[l * G + 0 * H + c * 16 + u] + bhh[l * G + 0 * H + c * 16 + u];
            q.y = bih[l * G + 1 * H + c * 16 + u] + bhh[l * G + 1 * H + c * 16 + u];
            q.z = bih[l * G + 2 * H + c * 16 + u] + bhh[l * G + 2 * H + c * 16 + u];
            q.w = bih[l * G + 3 * H + c * 16 + u] + bhh[l * G + 3 * H + c * 16 + u];
            bias4[u] = q;
        }
    } else {
        for (int idx = tid; idx < VOCAB * 16; idx += THR) {
            int v = idx >> 4, u = idx & 15;
            float4 q;
            q.x = g_table[v * G + 0 * H + c * 16 + u];
            q.y = g_table[v * G + 1 * H + c * 16 + u];
            q.z = g_table[v * G + 2 * H + c * 16 + u];
            q.w = g_table[v * G + 3 * H + c * 16 + u];
            tab4[idx] = q;
        }
    }
    __syncthreads();

    for (int t = 0; t < T; ++t) {
        if (l == 0 && tid < 64) tokI[tid] = x[tid * T + t];

        float acc[2][4][4];
#pragma unroll
        for (int a = 0; a < 2; ++a)
#pragma unroll
            for (int b = 0; b < 4; ++b)
#pragma unroll
                for (int q = 0; q < 4; ++q) acc[a][b][q] = 0.f;

        // ---- recurrent pass ----
        if (t > 0) {
            wait_done(l * T + (t - 1));
            const char* src = (const char*)g_hbf + (size_t)(l * T + t - 1) * 65536;
            copy_plane(smem + SB_BST, src, tid);
            copy_plane(smem + SB_BST + PLANE, src + 32768, tid);
            __syncthreads();
            gemm_term(sb + SB_WHH_HI, sb + SB_BST,         acc, mi, ni, kh, lane);
            gemm_term(sb + SB_WHH_HI, sb + SB_BST + PLANE, acc, mi, ni, kh, lane);
            gemm_term(sb + SB_WHH_LO, sb + SB_BST,         acc, mi, ni, kh, lane);
        }
        // ---- input pass ----
        if (l > 0) {
            wait_done((l - 1) * T + t);       // barrier also protects staging reuse
            const char* src = (const char*)g_hbf + (size_t)((l - 1) * T + t) * 65536;
            copy_plane(smem + SB_BST, src, tid);
            copy_plane(smem + SB_BST + PLANE, src + 32768, tid);
            __syncthreads();
            gemm_term(sb + SB_WIH_HI, sb + SB_BST,         acc, mi, ni, kh, lane);
            gemm_term(sb + SB_WIH_HI, sb + SB_BST + PLANE, acc, mi, ni, kh, lane);
            gemm_term(sb + SB_WIH_LO, sb + SB_BST,         acc, mi, ni, kh, lane);
        }
        __syncthreads();   // all staging reads done before gx (alias) writes

        // ---- split-K reduction into gx[64][68] ----
        if (kh == 0) {
#pragma unroll
            for (int ms = 0; ms < 2; ++ms) {
                int m = mi * 32 + ms * 16 + (lane >> 2);
#pragma unroll
                for (int ns = 0; ns < 4; ++ns) {
                    int b = ni * 32 + ns * 8 + (lane & 3) * 2;
                    *(float2*)(gx + m * 68 + b)       = make_float2(acc[ms][ns][0], acc[ms][ns][1]);
                    *(float2*)(gx + (m + 8) * 68 + b) = make_float2(acc[ms][ns][2], acc[ms][ns][3]);
                }
            }
        }
        __syncthreads();
        if (kh == 1) {
#pragma unroll
            for (int ms = 0; ms < 2; ++ms) {
                int m = mi * 32 + ms * 16 + (lane >> 2);
#pragma unroll
                for (int ns = 0; ns < 4; ++ns) {
                    int b = ni * 32 + ns * 8 + (lane & 3) * 2;
                    float2 g0 = *(float2*)(gx + m * 68 + b);
                    g0.x += acc[ms][ns][0]; g0.y += acc[ms][ns][1];
                    *(float2*)(gx + m * 68 + b) = g0;
                    float2 g1 = *(float2*)(gx + (m + 8) * 68 + b);
                    g1.x += acc[ms][ns][2]; g1.y += acc[ms][ns][3];
                    *(float2*)(gx + (m + 8) * 68 + b) = g1;
                }
            }
        }
        __syncthreads();

        // ---- cell update: thread = (u, 4 b's); coalesced bf16 h publish ----
        {
            const int u = tid & 15, grp = tid >> 4;
            char* dstP = (char*)g_hbf + (size_t)(l * T + t) * 65536;
            const int k = c * 16 + u;
            float4 bq = (l > 0) ? bias4[u] : make_float4(0.f, 0.f, 0.f, 0.f);
#pragma unroll
            for (int i = 0; i < 4; ++i) {
                int b = grp * 4 + i;
                float4 q = (l == 0) ? tab4[tokI[b] * 16 + u] : bq;
                float ig = gx[(0 * 16 + u) * 68 + b] + q.x;
                float fg = gx[(1 * 16 + u) * 68 + b] + q.y;
                float gg = gx[(2 * 16 + u) * 68 + b] + q.z;
                float og = gx[(3 * 16 + u) * 68 + b] + q.w;
                float cv = (t == 0) ? 0.f : cst[u * 68 + b];
                float cn = sigm(fg) * cv + sigm(ig) * tanha(gg);
                cst[u * 68 + b] = cn;
                float hv = sigm(og) * tanha(cn);
                __nv_bfloat16 hh = __float2bfloat16(hv);
                __nv_bfloat16 hl = __float2bfloat16(hv - __bfloat162float(hh));
                *(__nv_bfloat16*)(dstP + b * 512 + k * 2)         = hh;
                *(__nv_bfloat16*)(dstP + 32768 + b * 512 + k * 2) = hl;
                if (l == 7) g_hseq7[(size_t)t * 16384 + k * 64 + b] = hv;
            }
        }
        __threadfence();
        __syncthreads();
        if (tid == 0) atomicAdd(&g_done[l * T + t], 1);
    }
}

// ---------- final FC ----------
#define FC_SMEM_FLOATS (256 * 64 + 256 * 24 + 32)
__global__ void __launch_bounds__(256)
fc_kernel(const float* __restrict__ fcw, const float* __restrict__ fcb,
          float* __restrict__ out)
{
    extern __shared__ float fsm[];
    float* hs = fsm;
    float* ws = fsm + 256 * 64;
    float* bs = ws + 256 * 24;
    const int tid = threadIdx.x, t = blockIdx.x;

    const float* h7 = g_hseq7 + (size_t)t * H * B;
    {
        const float4* s = (const float4*)h7;
        float4* d = (float4*)hs;
        for (int i = tid; i < 4096; i += 256) d[i] = s[i];
    }
    for (int i = tid; i < VOCAB * H; i += 256) {
        int v = i >> 8, k = i & 255;
        ws[k * 24 + v] = fcw[i];
    }
    if (tid < VOCAB) bs[tid] = fcb[tid];
    __syncthreads();

    const int b = tid & 63, vg = tid >> 6;
    const int v0 = vg * 6;
    const int nv = (v0 + 6 <= VOCAB) ? 6 : (VOCAB - v0);
    float acc[6] = {0.f, 0.f, 0.f, 0.f, 0.f, 0.f};
#pragma unroll 4
    for (int k = 0; k < 256; ++k) {
        float a = hs[k * 64 + b];
#pragma unroll
        for (int j = 0; j < 6; ++j) acc[j] += a * ws[k * 24 + v0 + j];
    }
    for (int j = 0; j < nv; ++j)
        out[((size_t)b * T + t) * VOCAB + v0 + j] = acc[j] + bs[v0 + j];
}

// ---------- launch ----------
extern "C" void kernel_launch(void* const* d_in, const int* in_sizes, int n_in,
                              void* d_out, int out_size)
{
    const int*   x        = (const int*)d_in[0];
    const float* emb      = (const float*)d_in[1];
    const float* Wih0     = (const float*)d_in[2];
    const float* Wih_rest = (const float*)d_in[3];
    const float* Whh      = (const float*)d_in[4];
    const float* bih      = (const float*)d_in[5];
    const float* bhh      = (const float*)d_in[6];
    const float* fcw      = (const float*)d_in[7];
    const float* fcb      = (const float*)d_in[8];
    float*       out      = (float*)d_out;

    cudaFuncSetAttribute(lstm_main_kernel,
                         cudaFuncAttributeMaxDynamicSharedMemorySize, SMEM_BYTES);
    cudaFuncSetAttribute(fc_kernel,
                         cudaFuncAttributeMaxDynamicSharedMemorySize, FC_SMEM_FLOATS * 4);

    zero_done_kernel<<<16, 256>>>();
    build_table_kernel<<<(VOCAB * G + 255) / 256, 256>>>(emb, Wih0, bih, bhh);
    lstm_main_kernel<<<LAYERS * NC, THR, SMEM_BYTES>>>(x, Wih_rest, Whh, bih, bhh);
    fc_kernel<<<T, 256, FC_SMEM_FLOATS * 4>>>(fcw, fcb, out);
}

// round 11
// speedup vs baseline: 2.8044x; 1.1056x over previous
#include <cuda_runtime.h>
#include <cuda_bf16.h>
#include <cstdint>

#define LAYERS 8
#define T      512
#define B      64
#define H      256
#define G      1024
#define VOCAB  23
#define EMB    16
#define NC     16
#define THR    256

#define WSTR   528            // bytes per padded row (264 bf16)
#define PLANE  33792          // 64 rows * 528

// smem byte offsets
#define SB_WHH_HI 0
#define SB_WHH_LO 33792
#define SB_WIH_HI 67584
#define SB_WIH_LO 101376
#define SB_BST    135168      // staged h: hi plane, lo plane at +PLANE
#define SB_GX     135168      // alias over staging: f32 [64][68]
#define SB_GX2    152576      // second split-K buffer (alias, still inside staging)
#define SB_CST    202752      // f32 [16][68]
#define SB_TAB    207104      // float4 [23*16]
#define SB_BIAS   212992      // float4 [16]
#define SB_TOK    213248      // int [64]
#define SMEM_BYTES 213504

static __device__ __align__(128) __nv_bfloat16 g_hbf[(size_t)LAYERS * T * 2 * 16384];
static __device__ float g_hseq7[(size_t)T * H * B];
static __device__ float g_table[VOCAB * G];
static __device__ int   g_done[LAYERS * T];

// ---------- helpers ----------
__device__ __forceinline__ uint32_t smem_u32(const void* p) {
    uint32_t a;
    asm("{ .reg .u64 t; cvta.to.shared.u64 t, %1; cvt.u32.u64 %0, t; }" : "=r"(a) : "l"(p));
    return a;
}
__device__ __forceinline__ float tanha(float x) {
    float y; asm("tanh.approx.f32 %0, %1;" : "=f"(y) : "f"(x));
    return y;
}
__device__ __forceinline__ float sigm(float x) { return fmaf(0.5f, tanha(0.5f * x), 0.5f); }

__device__ __forceinline__ void wait_done(int idx) {
    if (threadIdx.x == 0) {
        volatile int* p = &g_done[idx];
        while (*p < NC) __nanosleep(32);
    }
    __syncthreads();
}

#define LDSM4(r0,r1,r2,r3,addr) \
    asm volatile("ldmatrix.sync.aligned.m8n8.x4.shared.b16 {%0,%1,%2,%3}, [%4];" \
                 : "=r"(r0),"=r"(r1),"=r"(r2),"=r"(r3) : "r"(addr))

#define MMA16816(c, a0,a1,a2,a3, b0,b1) \
    asm volatile("mma.sync.aligned.m16n8k16.row.col.f32.bf16.bf16.f32 " \
                 "{%0,%1,%2,%3},{%4,%5,%6,%7},{%8,%9},{%0,%1,%2,%3};" \
                 : "+f"((c)[0]),"+f"((c)[1]),"+f"((c)[2]),"+f"((c)[3]) \
                 : "r"(a0),"r"(a1),"r"(a2),"r"(a3),"r"(b0),"r"(b1))

// Load all fragments for one k16: A_hi(2 LDSM), A_lo(2), B_hi(2), B_lo(2).
__device__ __forceinline__ void load_frags(uint32_t* fa, uint32_t* fb,
    uint32_t aHi, uint32_t aLo, uint32_t bHi, uint32_t bLo, int k16)
{
    LDSM4(fa[0], fa[1], fa[2], fa[3],   aHi + k16 * 32);
    LDSM4(fa[4], fa[5], fa[6], fa[7],   aHi + 16 * WSTR + k16 * 32);
    LDSM4(fa[8], fa[9], fa[10], fa[11], aLo + k16 * 32);
    LDSM4(fa[12],fa[13],fa[14],fa[15],  aLo + 16 * WSTR + k16 * 32);
    LDSM4(fb[0], fb[1], fb[2], fb[3],   bHi + k16 * 32);
    LDSM4(fb[4], fb[5], fb[6], fb[7],   bHi + 16 * WSTR + k16 * 32);
    LDSM4(fb[8], fb[9], fb[10], fb[11], bLo + k16 * 32);
    LDSM4(fb[12],fb[13],fb[14],fb[15],  bLo + 16 * WSTR + k16 * 32);
}

// 24 MMAs: A_hi*B_hi + A_hi*B_lo + A_lo*B_hi into shared accumulators.
__device__ __forceinline__ void compute24(const uint32_t* fa, const uint32_t* fb,
                                          float (&acc)[2][4][4])
{
#pragma unroll
    for (int mh = 0; mh < 2; ++mh) {
        const uint32_t* ah = fa + mh * 4;
        const uint32_t* al = fa + 8 + mh * 4;
        const uint32_t* bh = fb;
        const uint32_t* bl = fb + 8;
        MMA16816(acc[mh][0], ah[0],ah[1],ah[2],ah[3], bh[0],bh[2]);
        MMA16816(acc[mh][1], ah[0],ah[1],ah[2],ah[3], bh[1],bh[3]);
        MMA16816(acc[mh][2], ah[0],ah[1],ah[2],ah[3], bh[4],bh[6]);
        MMA16816(acc[mh][3], ah[0],ah[1],ah[2],ah[3], bh[5],bh[7]);
        MMA16816(acc[mh][0], ah[0],ah[1],ah[2],ah[3], bl[0],bl[2]);
        MMA16816(acc[mh][1], ah[0],ah[1],ah[2],ah[3], bl[1],bl[3]);
        MMA16816(acc[mh][2], ah[0],ah[1],ah[2],ah[3], bl[4],bl[6]);
        MMA16816(acc[mh][3], ah[0],ah[1],ah[2],ah[3], bl[5],bl[7]);
        MMA16816(acc[mh][0], al[0],al[1],al[2],al[3], bh[0],bh[2]);
        MMA16816(acc[mh][1], al[0],al[1],al[2],al[3], bh[1],bh[3]);
        MMA16816(acc[mh][2], al[0],al[1],al[2],al[3], bh[4],bh[6]);
        MMA16816(acc[mh][3], al[0],al[1],al[2],al[3], bh[5],bh[7]);
    }
}

// One pass (3 fused terms), double-buffered fragments over the 8 k16 chunks.
__device__ __forceinline__ void gemm_fused3(
    uint32_t aHiP, uint32_t aLoP, uint32_t bHiP, uint32_t bLoP,
    float (&acc)[2][4][4], int mi, int ni, int kh, int lane)
{
    const uint32_t kOff = (uint32_t)(kh * 256) + ((lane >> 4) << 4);
    const uint32_t ar = (uint32_t)(mi * 32 + (lane & 15)) * WSTR + kOff;
    const uint32_t br = (uint32_t)(ni * 32 + (lane & 15)) * WSTR + kOff;
    const uint32_t aHi = aHiP + ar, aLo = aLoP + ar;
    const uint32_t bHi = bHiP + br, bLo = bLoP + br;
    uint32_t fa[2][16], fb[2][16];
    load_frags(fa[0], fb[0], aHi, aLo, bHi, bLo, 0);
#pragma unroll
    for (int k16 = 0; k16 < 8; ++k16) {
        const int cur = k16 & 1;
        if (k16 < 7) load_frags(fa[cur ^ 1], fb[cur ^ 1], aHi, aLo, bHi, bLo, k16 + 1);
        compute24(fa[cur], fb[cur], acc);
    }
}

// async-stage one dense 32KB global plane into padded smem plane
__device__ __forceinline__ void copy_plane_async(uint32_t dstS, const char* src, int tid) {
#pragma unroll
    for (int u = 0; u < 8; ++u) {
        int i = tid + u * THR;
        int b = i >> 5, kc = i & 31;
        asm volatile("cp.async.cg.shared.global [%0], [%1], 16;"
                     :: "r"(dstS + (uint32_t)(b * WSTR + kc * 16)),
                        "l"(src + b * 512 + kc * 16) : "memory");
    }
}
__device__ __forceinline__ void cpasync_flush() {
    asm volatile("cp.async.commit_group;" ::: "memory");
    asm volatile("cp.async.wait_group 0;" ::: "memory");
}

// ---------- prelude ----------
__global__ void zero_done_kernel() {
    int i = blockIdx.x * blockDim.x + threadIdx.x;
    if (i < LAYERS * T) g_done[i] = 0;
}
__global__ void build_table_kernel(const float* __restrict__ emb, const float* __restrict__ Wih0,
                                   const float* __restrict__ bih, const float* __restrict__ bhh) {
    int idx = blockIdx.x * blockDim.x + threadIdx.x;
    if (idx >= VOCAB * G) return;
    int v = idx / G, j = idx % G;
    float s = bih[j] + bhh[j];
#pragma unroll
    for (int e = 0; e < EMB; ++e) s += emb[v * EMB + e] * Wih0[j * EMB + e];
    g_table[idx] = s;
}

// ---------- main persistent wavefront kernel ----------
extern "C" __global__ void __launch_bounds__(THR, 1)
lstm_main_kernel(const int* __restrict__ x,
                 const float* __restrict__ Wih_rest,
                 const float* __restrict__ Whh,
                 const float* __restrict__ bih,
                 const float* __restrict__ bhh)
{
    extern __shared__ char smem[];
    const uint32_t sb = smem_u32(smem);
    const int tid  = threadIdx.x;
    const int warp = tid >> 5, lane = tid & 31;
    const int l = blockIdx.x >> 4;
    const int c = blockIdx.x & 15;          // unit block: units c*16 .. c*16+15
    const int kh = warp >> 2, mi = (warp >> 1) & 1, ni = warp & 1;

    float*  gx    = (float*)(smem + SB_GX);     // [64][68]
    float*  gx2   = (float*)(smem + SB_GX2);    // [64][68]
    float*  cst   = (float*)(smem + SB_CST);    // [16][68]
    float4* tab4  = (float4*)(smem + SB_TAB);
    float4* bias4 = (float4*)(smem + SB_BIAS);
    int*    tokI  = (int*)(smem + SB_TOK);

    // ---- resident weights: bf16 hi/lo planes, rows r = gate*16 + u, padded ----
    {
        const float* Wl = Whh + (size_t)l * G * H;
        for (int idx = tid; idx < 64 * 256; idx += THR) {
            int r = idx >> 8, k = idx & 255;
            int jg = (r >> 4) * H + c * 16 + (r & 15);
            float w = Wl[(size_t)jg * H + k];
            __nv_bfloat16 wh = __float2bfloat16(w);
            *(__nv_bfloat16*)(smem + SB_WHH_HI + r * WSTR + k * 2) = wh;
            *(__nv_bfloat16*)(smem + SB_WHH_LO + r * WSTR + k * 2) =
                __float2bfloat16(w - __bfloat162float(wh));
        }
    }
    if (l > 0) {
        const float* Wl = Wih_rest + (size_t)(l - 1) * G * H;
        for (int idx = tid; idx < 64 * 256; idx += THR) {
            int r = idx >> 8, k = idx & 255;
            int jg = (r >> 4) * H + c * 16 + (r & 15);
            float w = Wl[(size_t)jg * H + k];
            __nv_bfloat16 wh = __float2bfloat16(w);
            *(__nv_bfloat16*)(smem + SB_WIH_HI + r * WSTR + k * 2) = wh;
            *(__nv_bfloat16*)(smem + SB_WIH_LO + r * WSTR + k * 2) =
                __float2bfloat16(w - __bfloat162float(wh));
        }
        if (tid < 16) {
            int u = tid;
            float4 q;
            q.x = bih[l * G + 0 * H + c * 16 + u] + bhh[l * G + 0 * H + c * 16 + u];
            q.y = bih[l * G + 1 * H + c * 16 + u] + bhh[l * G + 1 * H + c * 16 + u];
            q.z = bih[l * G + 2 * H + c * 16 + u] + bhh[l * G + 2 * H + c * 16 + u];
            q.w = bih[l * G + 3 * H + c * 16 + u] + bhh[l * G + 3 * H + c * 16 + u];
            bias4[u] = q;
        }
    } else {
        for (int idx = tid; idx < VOCAB * 16; idx += THR) {
            int v = idx >> 4, u = idx & 15;
            float4 q;
            q.x = g_table[v * G + 0 * H + c * 16 + u];
            q.y = g_table[v * G + 1 * H + c * 16 + u];
            q.z = g_table[v * G + 2 * H + c * 16 + u];
            q.w = g_table[v * G + 3 * H + c * 16 + u];
            tab4[idx] = q;
        }
    }
    __syncthreads();

    for (int t = 0; t < T; ++t) {
        if (l == 0 && tid < 64) tokI[tid] = x[tid * T + t];

        float acc[2][4][4];
#pragma unroll
        for (int a = 0; a < 2; ++a)
#pragma unroll
            for (int b = 0; b < 4; ++b)
#pragma unroll
                for (int q = 0; q < 4; ++q) acc[a][b][q] = 0.f;

        // ---- recurrent pass ----
        if (t > 0) {
            wait_done(l * T + (t - 1));
            const char* src = (const char*)g_hbf + (size_t)(l * T + t - 1) * 65536;
            copy_plane_async(sb + SB_BST, src, tid);
            copy_plane_async(sb + SB_BST + PLANE, src + 32768, tid);
            cpasync_flush();
            __syncthreads();
            gemm_fused3(sb + SB_WHH_HI, sb + SB_WHH_LO,
                        sb + SB_BST, sb + SB_BST + PLANE, acc, mi, ni, kh, lane);
        }
        // ---- input pass ----
        if (l > 0) {
            wait_done((l - 1) * T + t);       // barrier also protects staging reuse
            const char* src = (const char*)g_hbf + (size_t)((l - 1) * T + t) * 65536;
            copy_plane_async(sb + SB_BST, src, tid);
            copy_plane_async(sb + SB_BST + PLANE, src + 32768, tid);
            cpasync_flush();
            __syncthreads();
            gemm_fused3(sb + SB_WIH_HI, sb + SB_WIH_LO,
                        sb + SB_BST, sb + SB_BST + PLANE, acc, mi, ni, kh, lane);
        }
        __syncthreads();   // all staging reads done before gx/gx2 (alias) writes

        // ---- split-K: kh=0 -> gx, kh=1 -> gx2 (disjoint, single sync) ----
        {
            float* dst = (kh == 0) ? gx : gx2;
#pragma unroll
            for (int ms = 0; ms < 2; ++ms) {
                int m = mi * 32 + ms * 16 + (lane >> 2);
#pragma unroll
                for (int ns = 0; ns < 4; ++ns) {
                    int b = ni * 32 + ns * 8 + (lane & 3) * 2;
                    *(float2*)(dst + m * 68 + b)       = make_float2(acc[ms][ns][0], acc[ms][ns][1]);
                    *(float2*)(dst + (m + 8) * 68 + b) = make_float2(acc[ms][ns][2], acc[ms][ns][3]);
                }
            }
        }
        __syncthreads();

        // ---- cell update: thread = (u, 4 b's); coalesced bf16 h publish ----
        {
            const int u = tid & 15, grp = tid >> 4;
            char* dstP = (char*)g_hbf + (size_t)(l * T + t) * 65536;
            const int k = c * 16 + u;
            float4 bq = (l > 0) ? bias4[u] : make_float4(0.f, 0.f, 0.f, 0.f);
#pragma unroll
            for (int i = 0; i < 4; ++i) {
                int b = grp * 4 + i;
                float4 q = (l == 0) ? tab4[tokI[b] * 16 + u] : bq;
                float ig = gx[(0 * 16 + u) * 68 + b] + gx2[(0 * 16 + u) * 68 + b] + q.x;
                float fg = gx[(1 * 16 + u) * 68 + b] + gx2[(1 * 16 + u) * 68 + b] + q.y;
                float gg = gx[(2 * 16 + u) * 68 + b] + gx2[(2 * 16 + u) * 68 + b] + q.z;
                float og = gx[(3 * 16 + u) * 68 + b] + gx2[(3 * 16 + u) * 68 + b] + q.w;
                float cv = (t == 0) ? 0.f : cst[u * 68 + b];
                float cn = sigm(fg) * cv + sigm(ig) * tanha(gg);
                cst[u * 68 + b] = cn;
                float hv = sigm(og) * tanha(cn);
                __nv_bfloat16 hh = __float2bfloat16(hv);
                __nv_bfloat16 hl = __float2bfloat16(hv - __bfloat162float(hh));
                *(__nv_bfloat16*)(dstP + b * 512 + k * 2)         = hh;
                *(__nv_bfloat16*)(dstP + 32768 + b * 512 + k * 2) = hl;
                if (l == 7) g_hseq7[(size_t)t * 16384 + k * 64 + b] = hv;
            }
        }
        __threadfence();
        __syncthreads();
        if (tid == 0) atomicAdd(&g_done[l * T + t], 1);
    }
}

// ---------- final FC ----------
#define FC_SMEM_FLOATS (256 * 64 + 256 * 24 + 32)
__global__ void __launch_bounds__(256)
fc_kernel(const float* __restrict__ fcw, const float* __restrict__ fcb,
          float* __restrict__ out)
{
    extern __shared__ float fsm[];
    float* hs = fsm;
    float* ws = fsm + 256 * 64;
    float* bs = ws + 256 * 24;
    const int tid = threadIdx.x, t = blockIdx.x;

    const float* h7 = g_hseq7 + (size_t)t * H * B;
    {
        const float4* s = (const float4*)h7;
        float4* d = (float4*)hs;
        for (int i = tid; i < 4096; i += 256) d[i] = s[i];
    }
    for (int i = tid; i < VOCAB * H; i += 256) {
        int v = i >> 8, k = i & 255;
        ws[k * 24 + v] = fcw[i];
    }
    if (tid < VOCAB) bs[tid] = fcb[tid];
    __syncthreads();

    const int b = tid & 63, vg = tid >> 6;
    const int v0 = vg * 6;
    const int nv = (v0 + 6 <= VOCAB) ? 6 : (VOCAB - v0);
    float acc[6] = {0.f, 0.f, 0.f, 0.f, 0.f, 0.f};
#pragma unroll 4
    for (int k = 0; k < 256; ++k) {
        float a = hs[k * 64 + b];
#pragma unroll
        for (int j = 0; j < 6; ++j) acc[j] += a * ws[k * 24 + v0 + j];
    }
    for (int j = 0; j < nv; ++j)
        out[((size_t)b * T + t) * VOCAB + v0 + j] = acc[j] + bs[v0 + j];
}

// ---------- launch ----------
extern "C" void kernel_launch(void* const* d_in, const int* in_sizes, int n_in,
                              void* d_out, int out_size)
{
    const int*   x        = (const int*)d_in[0];
    const float* emb      = (const float*)d_in[1];
    const float* Wih0     = (const float*)d_in[2];
    const float* Wih_rest = (const float*)d_in[3];
    const float* Whh      = (const float*)d_in[4];
    const float* bih      = (const float*)d_in[5];
    const float* bhh      = (const float*)d_in[6];
    const float* fcw      = (const float*)d_in[7];
    const float* fcb      = (const float*)d_in[8];
    float*       out      = (float*)d_out;

    cudaFuncSetAttribute(lstm_main_kernel,
                         cudaFuncAttributeMaxDynamicSharedMemorySize, SMEM_BYTES);
    cudaFuncSetAttribute(fc_kernel,
                         cudaFuncAttributeMaxDynamicSharedMemorySize, FC_SMEM_FLOATS * 4);

    zero_done_kernel<<<16, 256>>>();
    build_table_kernel<<<(VOCAB * G + 255) / 256, 256>>>(emb, Wih0, bih, bhh);
    lstm_main_kernel<<<LAYERS * NC, THR, SMEM_BYTES>>>(x, Wih_rest, Whh, bih, bhh);
    fc_kernel<<<T, 256, FC_SMEM_FLOATS * 4>>>(fcw, fcb, out);
}

// round 12
// speedup vs baseline: 2.9899x; 1.0661x over previous
#include <cuda_runtime.h>
#include <cuda_bf16.h>
#include <cstdint>

#define LAYERS 8
#define T      512
#define B      64
#define H      256
#define G      1024
#define VOCAB  23
#define EMB    16
#define NC     16
#define THR    256

#define WSTR   528            // bytes per padded row (264 bf16)
#define PLANE  33792          // 64 rows * 528

// smem byte offsets
#define SB_WHH_HI 0
#define SB_WHH_LO 33792
#define SB_WIH_HI 67584
#define SB_WIH_LO 101376
#define SB_BUF0   135168      // staging plane buffer 0 (padded rows)
#define SB_BUF1   168960      // staging plane buffer 1
#define SB_GX     135168      // alias buf0: f32 [64][68]
#define SB_GX2    168960      // alias buf1: f32 [64][68]
#define SB_CST    202752      // f32 [16][68]
#define SB_TAB    207104      // float4 [23*16]
#define SB_BIAS   212992      // float4 [16]
#define SB_TOK    213248      // int [64]
#define SMEM_BYTES 213504

static __device__ __align__(128) __nv_bfloat16 g_hbf[(size_t)LAYERS * T * 2 * 16384];
static __device__ float g_hseq7[(size_t)T * H * B];
static __device__ float g_table[VOCAB * G];
static __device__ int   g_done[LAYERS * T];

// ---------- helpers ----------
__device__ __forceinline__ uint32_t smem_u32(const void* p) {
    uint32_t a;
    asm("{ .reg .u64 t; cvta.to.shared.u64 t, %1; cvt.u32.u64 %0, t; }" : "=r"(a) : "l"(p));
    return a;
}
__device__ __forceinline__ float tanha(float x) {
    float y; asm("tanh.approx.f32 %0, %1;" : "=f"(y) : "f"(x));
    return y;
}
__device__ __forceinline__ float sigm(float x) { return fmaf(0.5f, tanha(0.5f * x), 0.5f); }

__device__ __forceinline__ void wait_done(int idx) {
    if (threadIdx.x == 0) {
        volatile int* p = &g_done[idx];
        while (*p < NC) __nanosleep(32);
    }
    __syncthreads();
}

#define LDSM4(r0,r1,r2,r3,addr) \
    asm volatile("ldmatrix.sync.aligned.m8n8.x4.shared.b16 {%0,%1,%2,%3}, [%4];" \
                 : "=r"(r0),"=r"(r1),"=r"(r2),"=r"(r3) : "r"(addr))

#define MMA16816(c, a0,a1,a2,a3, b0,b1) \
    asm volatile("mma.sync.aligned.m16n8k16.row.col.f32.bf16.bf16.f32 " \
                 "{%0,%1,%2,%3},{%4,%5,%6,%7},{%8,%9},{%0,%1,%2,%3};" \
                 : "+f"((c)[0]),"+f"((c)[1]),"+f"((c)[2]),"+f"((c)[3]) \
                 : "r"(a0),"r"(a1),"r"(a2),"r"(a3),"r"(b0),"r"(b1))

// hi-phase: acc += A_hi*B + A_lo*B over 8 k16 chunks; persists A_hi fragments in fah.
__device__ __forceinline__ void phase_hi(
    uint32_t aHiP, uint32_t aLoP, uint32_t bufP,
    float (&acc)[2][4][4], uint32_t (&fah)[8][8],
    uint32_t ar, uint32_t br)
{
    const uint32_t aHi = aHiP + ar, aLo = aLoP + ar, bP = bufP + br;
    uint32_t fal[2][8], fb[2][8];
    LDSM4(fah[0][0],fah[0][1],fah[0][2],fah[0][3], aHi);
    LDSM4(fah[0][4],fah[0][5],fah[0][6],fah[0][7], aHi + 16 * WSTR);
    LDSM4(fal[0][0],fal[0][1],fal[0][2],fal[0][3], aLo);
    LDSM4(fal[0][4],fal[0][5],fal[0][6],fal[0][7], aLo + 16 * WSTR);
    LDSM4(fb[0][0],fb[0][1],fb[0][2],fb[0][3], bP);
    LDSM4(fb[0][4],fb[0][5],fb[0][6],fb[0][7], bP + 16 * WSTR);
#pragma unroll
    for (int k = 0; k < 8; ++k) {
        const int cur = k & 1;
        if (k < 7) {
            const int nx = cur ^ 1;
            LDSM4(fah[k+1][0],fah[k+1][1],fah[k+1][2],fah[k+1][3], aHi + (k+1)*32);
            LDSM4(fah[k+1][4],fah[k+1][5],fah[k+1][6],fah[k+1][7], aHi + 16*WSTR + (k+1)*32);
            LDSM4(fal[nx][0],fal[nx][1],fal[nx][2],fal[nx][3], aLo + (k+1)*32);
            LDSM4(fal[nx][4],fal[nx][5],fal[nx][6],fal[nx][7], aLo + 16*WSTR + (k+1)*32);
            LDSM4(fb[nx][0],fb[nx][1],fb[nx][2],fb[nx][3], bP + (k+1)*32);
            LDSM4(fb[nx][4],fb[nx][5],fb[nx][6],fb[nx][7], bP + 16*WSTR + (k+1)*32);
        }
#pragma unroll
        for (int mh = 0; mh < 2; ++mh) {
            const uint32_t* ah = &fah[k][mh * 4];
            const uint32_t* al = &fal[cur][mh * 4];
            const uint32_t* b  = fb[cur];
            MMA16816(acc[mh][0], ah[0],ah[1],ah[2],ah[3], b[0],b[2]);
            MMA16816(acc[mh][1], ah[0],ah[1],ah[2],ah[3], b[1],b[3]);
            MMA16816(acc[mh][2], ah[0],ah[1],ah[2],ah[3], b[4],b[6]);
            MMA16816(acc[mh][3], ah[0],ah[1],ah[2],ah[3], b[5],b[7]);
            MMA16816(acc[mh][0], al[0],al[1],al[2],al[3], b[0],b[2]);
            MMA16816(acc[mh][1], al[0],al[1],al[2],al[3], b[1],b[3]);
            MMA16816(acc[mh][2], al[0],al[1],al[2],al[3], b[4],b[6]);
            MMA16816(acc[mh][3], al[0],al[1],al[2],al[3], b[5],b[7]);
        }
    }
}

// lo-phase: acc += A_hi(persisted)*B_lo over 8 k16 chunks.
__device__ __forceinline__ void phase_lo(
    uint32_t bufP, float (&acc)[2][4][4], const uint32_t (&fah)[8][8], uint32_t br)
{
    const uint32_t bP = bufP + br;
    uint32_t fb[2][8];
    LDSM4(fb[0][0],fb[0][1],fb[0][2],fb[0][3], bP);
    LDSM4(fb[0][4],fb[0][5],fb[0][6],fb[0][7], bP + 16 * WSTR);
#pragma unroll
    for (int k = 0; k < 8; ++k) {
        const int cur = k & 1;
        if (k < 7) {
            const int nx = cur ^ 1;
            LDSM4(fb[nx][0],fb[nx][1],fb[nx][2],fb[nx][3], bP + (k+1)*32);
            LDSM4(fb[nx][4],fb[nx][5],fb[nx][6],fb[nx][7], bP + 16*WSTR + (k+1)*32);
        }
#pragma unroll
        for (int mh = 0; mh < 2; ++mh) {
            const uint32_t* ah = &fah[k][mh * 4];
            const uint32_t* b  = fb[cur];
            MMA16816(acc[mh][0], ah[0],ah[1],ah[2],ah[3], b[0],b[2]);
            MMA16816(acc[mh][1], ah[0],ah[1],ah[2],ah[3], b[1],b[3]);
            MMA16816(acc[mh][2], ah[0],ah[1],ah[2],ah[3], b[4],b[6]);
            MMA16816(acc[mh][3], ah[0],ah[1],ah[2],ah[3], b[5],b[7]);
        }
    }
}

// async-stage one dense 32KB global plane into a padded smem plane; commits a group.
__device__ __forceinline__ void stage(uint32_t dstS, const char* src, int tid) {
#pragma unroll
    for (int u = 0; u < 8; ++u) {
        int i = tid + u * THR;
        int b = i >> 5, kc = i & 31;
        asm volatile("cp.async.cg.shared.global [%0], [%1], 16;"
                     :: "r"(dstS + (uint32_t)(b * WSTR + kc * 16)),
                        "l"(src + b * 512 + kc * 16) : "memory");
    }
    asm volatile("cp.async.commit_group;" ::: "memory");
}
#define CP_WAIT1() asm volatile("cp.async.wait_group 1;" ::: "memory")
#define CP_WAIT0() asm volatile("cp.async.wait_group 0;" ::: "memory")

// ---------- prelude ----------
__global__ void zero_done_kernel() {
    int i = blockIdx.x * blockDim.x + threadIdx.x;
    if (i < LAYERS * T) g_done[i] = 0;
}
__global__ void build_table_kernel(const float* __restrict__ emb, const float* __restrict__ Wih0,
                                   const float* __restrict__ bih, const float* __restrict__ bhh) {
    int idx = blockIdx.x * blockDim.x + threadIdx.x;
    if (idx >= VOCAB * G) return;
    int v = idx / G, j = idx % G;
    float s = bih[j] + bhh[j];
#pragma unroll
    for (int e = 0; e < EMB; ++e) s += emb[v * EMB + e] * Wih0[j * EMB + e];
    g_table[idx] = s;
}

// ---------- main persistent wavefront kernel ----------
extern "C" __global__ void __launch_bounds__(THR, 1)
lstm_main_kernel(const int* __restrict__ x,
                 const float* __restrict__ Wih_rest,
                 const float* __restrict__ Whh,
                 const float* __restrict__ bih,
                 const float* __restrict__ bhh)
{
    extern __shared__ char smem[];
    const uint32_t sb = smem_u32(smem);
    const int tid  = threadIdx.x;
    const int warp = tid >> 5, lane = tid & 31;
    const int l = blockIdx.x >> 4;
    const int c = blockIdx.x & 15;          // unit block: units c*16 .. c*16+15
    const int kh = warp >> 2, mi = (warp >> 1) & 1, ni = warp & 1;

    float*  gx    = (float*)(smem + SB_GX);     // [64][68]
    float*  gx2   = (float*)(smem + SB_GX2);    // [64][68]
    float*  cst   = (float*)(smem + SB_CST);    // [16][68]
    float4* tab4  = (float4*)(smem + SB_TAB);
    float4* bias4 = (float4*)(smem + SB_BIAS);
    int*    tokI  = (int*)(smem + SB_TOK);

    // per-warp fragment base offsets
    const uint32_t kOff = (uint32_t)(kh * 256) + ((lane >> 4) << 4);
    const uint32_t ar = (uint32_t)(mi * 32 + (lane & 15)) * WSTR + kOff;
    const uint32_t br = (uint32_t)(ni * 32 + (lane & 15)) * WSTR + kOff;

    // ---- resident weights: bf16 hi/lo planes, rows r = gate*16 + u, padded ----
    {
        const float* Wl = Whh + (size_t)l * G * H;
        for (int idx = tid; idx < 64 * 256; idx += THR) {
            int r = idx >> 8, k = idx & 255;
            int jg = (r >> 4) * H + c * 16 + (r & 15);
            float w = Wl[(size_t)jg * H + k];
            __nv_bfloat16 wh = __float2bfloat16(w);
            *(__nv_bfloat16*)(smem + SB_WHH_HI + r * WSTR + k * 2) = wh;
            *(__nv_bfloat16*)(smem + SB_WHH_LO + r * WSTR + k * 2) =
                __float2bfloat16(w - __bfloat162float(wh));
        }
    }
    if (l > 0) {
        const float* Wl = Wih_rest + (size_t)(l - 1) * G * H;
        for (int idx = tid; idx < 64 * 256; idx += THR) {
            int r = idx >> 8, k = idx & 255;
            int jg = (r >> 4) * H + c * 16 + (r & 15);
            float w = Wl[(size_t)jg * H + k];
            __nv_bfloat16 wh = __float2bfloat16(w);
            *(__nv_bfloat16*)(smem + SB_WIH_HI + r * WSTR + k * 2) = wh;
            *(__nv_bfloat16*)(smem + SB_WIH_LO + r * WSTR + k * 2) =
                __float2bfloat16(w - __bfloat162float(wh));
        }
        if (tid < 16) {
            int u = tid;
            float4 q;
            q.x = bih[l * G + 0 * H + c * 16 + u] + bhh[l * G + 0 * H + c * 16 + u];
            q.y = bih[l * G + 1 * H + c * 16 + u] + bhh[l * G + 1 * H + c * 16 + u];
            q.z = bih[l * G + 2 * H + c * 16 + u] + bhh[l * G + 2 * H + c * 16 + u];
            q.w = bih[l * G + 3 * H + c * 16 + u] + bhh[l * G + 3 * H + c * 16 + u];
            bias4[u] = q;
        }
    } else {
        for (int idx = tid; idx < VOCAB * 16; idx += THR) {
            int v = idx >> 4, u = idx & 15;
            float4 q;
            q.x = g_table[v * G + 0 * H + c * 16 + u];
            q.y = g_table[v * G + 1 * H + c * 16 + u];
            q.z = g_table[v * G + 2 * H + c * 16 + u];
            q.w = g_table[v * G + 3 * H + c * 16 + u];
            tab4[idx] = q;
        }
    }
    __syncthreads();

    for (int t = 0; t < T; ++t) {
        if (l == 0 && tid < 64) tokI[tid] = x[tid * T + t];

        float acc[2][4][4];
#pragma unroll
        for (int a = 0; a < 2; ++a)
#pragma unroll
            for (int b = 0; b < 4; ++b)
#pragma unroll
                for (int q = 0; q < 4; ++q) acc[a][b][q] = 0.f;
        uint32_t fah[8][8];

        const bool rec = (t > 0), inp = (l > 0);
        const char* recsrc = (const char*)g_hbf + (size_t)(l * T + t - 1) * 65536;
        const char* insrc  = (const char*)g_hbf + (size_t)((l - 1) * T + t) * 65536;

        if (rec && inp) {
            wait_done(l * T + (t - 1));
            stage(sb + SB_BUF0, recsrc, tid);                 // G1 rec_hi
            wait_done((l - 1) * T + t);
            stage(sb + SB_BUF1, recsrc + 32768, tid);         // G2 rec_lo
            CP_WAIT1(); __syncthreads();                      // buf0 = rec_hi ready
            phase_hi(sb + SB_WHH_HI, sb + SB_WHH_LO, sb + SB_BUF0, acc, fah, ar, br);
            __syncthreads();                                  // buf0 free
            stage(sb + SB_BUF0, insrc, tid);                  // G3 in_hi (overlaps)
            CP_WAIT1(); __syncthreads();                      // buf1 = rec_lo ready
            phase_lo(sb + SB_BUF1, acc, fah, br);
            __syncthreads();                                  // buf1 free
            stage(sb + SB_BUF1, insrc + 32768, tid);          // G4 in_lo (overlaps)
            CP_WAIT1(); __syncthreads();                      // buf0 = in_hi ready
            phase_hi(sb + SB_WIH_HI, sb + SB_WIH_LO, sb + SB_BUF0, acc, fah, ar, br);
            CP_WAIT0(); __syncthreads();                      // buf1 = in_lo ready; buf0 reads done
            phase_lo(sb + SB_BUF1, acc, fah, br);
        } else if (rec) {
            wait_done(l * T + (t - 1));
            stage(sb + SB_BUF0, recsrc, tid);
            stage(sb + SB_BUF1, recsrc + 32768, tid);
            CP_WAIT1(); __syncthreads();
            phase_hi(sb + SB_WHH_HI, sb + SB_WHH_LO, sb + SB_BUF0, acc, fah, ar, br);
            CP_WAIT0(); __syncthreads();
            phase_lo(sb + SB_BUF1, acc, fah, br);
        } else if (inp) {
            wait_done((l - 1) * T + t);
            stage(sb + SB_BUF0, insrc, tid);
            stage(sb + SB_BUF1, insrc + 32768, tid);
            CP_WAIT1(); __syncthreads();
            phase_hi(sb + SB_WIH_HI, sb + SB_WIH_LO, sb + SB_BUF0, acc, fah, ar, br);
            CP_WAIT0(); __syncthreads();
            phase_lo(sb + SB_BUF1, acc, fah, br);
        }
        __syncthreads();   // all staging reads done before gx/gx2 (alias) writes

        // ---- split-K: kh=0 -> gx, kh=1 -> gx2 (disjoint, single sync) ----
        {
            float* dst = (kh == 0) ? gx : gx2;
#pragma unroll
            for (int ms = 0; ms < 2; ++ms) {
                int m = mi * 32 + ms * 16 + (lane >> 2);
#pragma unroll
                for (int ns = 0; ns < 4; ++ns) {
                    int b = ni * 32 + ns * 8 + (lane & 3) * 2;
                    *(float2*)(dst + m * 68 + b)       = make_float2(acc[ms][ns][0], acc[ms][ns][1]);
                    *(float2*)(dst + (m + 8) * 68 + b) = make_float2(acc[ms][ns][2], acc[ms][ns][3]);
                }
            }
        }
        __syncthreads();

        // ---- cell update: thread = (u, 4 b's); coalesced bf16 h publish ----
        {
            const int u = tid & 15, grp = tid >> 4;
            char* dstP = (char*)g_hbf + (size_t)(l * T + t) * 65536;
            const int k = c * 16 + u;
            float4 bq = (l > 0) ? bias4[u] : make_float4(0.f, 0.f, 0.f, 0.f);
#pragma unroll
            for (int i = 0; i < 4; ++i) {
                int b = grp * 4 + i;
                float4 q = (l == 0) ? tab4[tokI[b] * 16 + u] : bq;
                float ig = gx[(0 * 16 + u) * 68 + b] + gx2[(0 * 16 + u) * 68 + b] + q.x;
                float fg = gx[(1 * 16 + u) * 68 + b] + gx2[(1 * 16 + u) * 68 + b] + q.y;
                float gg = gx[(2 * 16 + u) * 68 + b] + gx2[(2 * 16 + u) * 68 + b] + q.z;
                float og = gx[(3 * 16 + u) * 68 + b] + gx2[(3 * 16 + u) * 68 + b] + q.w;
                float cv = (t == 0) ? 0.f : cst[u * 68 + b];
                float cn = sigm(fg) * cv + sigm(ig) * tanha(gg);
                cst[u * 68 + b] = cn;
                float hv = sigm(og) * tanha(cn);
                __nv_bfloat16 hh = __float2bfloat16(hv);
                __nv_bfloat16 hl = __float2bfloat16(hv - __bfloat162float(hh));
                *(__nv_bfloat16*)(dstP + b * 512 + k * 2)         = hh;
                *(__nv_bfloat16*)(dstP + 32768 + b * 512 + k * 2) = hl;
                if (l == 7) g_hseq7[(size_t)t * 16384 + k * 64 + b] = hv;
            }
        }
        __threadfence();
        __syncthreads();
        if (tid == 0) atomicAdd(&g_done[l * T + t], 1);
    }
}

// ---------- final FC ----------
#define FC_SMEM_FLOATS (256 * 64 + 256 * 24 + 32)
__global__ void __launch_bounds__(256)
fc_kernel(const float* __restrict__ fcw, const float* __restrict__ fcb,
          float* __restrict__ out)
{
    extern __shared__ float fsm[];
    float* hs = fsm;
    float* ws = fsm + 256 * 64;
    float* bs = ws + 256 * 24;
    const int tid = threadIdx.x, t = blockIdx.x;

    const float* h7 = g_hseq7 + (size_t)t * H * B;
    {
        const float4* s = (const float4*)h7;
        float4* d = (float4*)hs;
        for (int i = tid; i < 4096; i += 256) d[i] = s[i];
    }
    for (int i = tid; i < VOCAB * H; i += 256) {
        int v = i >> 8, k = i & 255;
        ws[k * 24 + v] = fcw[i];
    }
    if (tid < VOCAB) bs[tid] = fcb[tid];
    __syncthreads();

    const int b = tid & 63, vg = tid >> 6;
    const int v0 = vg * 6;
    const int nv = (v0 + 6 <= VOCAB) ? 6 : (VOCAB - v0);
    float acc[6] = {0.f, 0.f, 0.f, 0.f, 0.f, 0.f};
#pragma unroll 4
    for (int k = 0; k < 256; ++k) {
        float a = hs[k * 64 + b];
#pragma unroll
        for (int j = 0; j < 6; ++j) acc[j] += a * ws[k * 24 + v0 + j];
    }
    for (int j = 0; j < nv; ++j)
        out[((size_t)b * T + t) * VOCAB + v0 + j] = acc[j] + bs[v0 + j];
}

// ---------- launch ----------
extern "C" void kernel_launch(void* const* d_in, const int* in_sizes, int n_in,
                              void* d_out, int out_size)
{
    const int*   x        = (const int*)d_in[0];
    const float* emb      = (const float*)d_in[1];
    const float* Wih0     = (const float*)d_in[2];
    const float* Wih_rest = (const float*)d_in[3];
    const float* Whh      = (const float*)d_in[4];
    const float* bih      = (const float*)d_in[5];
    const float* bhh      = (const float*)d_in[6];
    const float* fcw      = (const float*)d_in[7];
    const float* fcb      = (const float*)d_in[8];
    float*       out      = (float*)d_out;

    cudaFuncSetAttribute(lstm_main_kernel,
                         cudaFuncAttributeMaxDynamicSharedMemorySize, SMEM_BYTES);
    cudaFuncSetAttribute(fc_kernel,
                         cudaFuncAttributeMaxDynamicSharedMemorySize, FC_SMEM_FLOATS * 4);

    zero_done_kernel<<<16, 256>>>();
    build_table_kernel<<<(VOCAB * G + 255) / 256, 256>>>(emb, Wih0, bih, bhh);
    lstm_main_kernel<<<LAYERS * NC, THR, SMEM_BYTES>>>(x, Wih_rest, Whh, bih, bhh);
    fc_kernel<<<T, 256, FC_SMEM_FLOATS * 4>>>(fcw, fcb, out);
}

// round 13
// speedup vs baseline: 3.0840x; 1.0315x over previous
#include <cuda_runtime.h>
#include <cuda_bf16.h>
#include <cstdint>

#define LAYERS 8
#define T      512
#define B      64
#define H      256
#define G      1024
#define VOCAB  23
#define EMB    16
#define NC     16
#define THR    256

#define WSTR   528            // bytes per padded row (264 bf16)

// smem byte offsets
#define SB_WHH_LO 0
#define SB_WIH_LO 33792
#define SB_BUF0   67584
#define SB_BUF1   101376
#define SB_BUF2   135168
#define SB_GX     168960      // f32 [64][68]
#define SB_GX2    186368      // f32 [64][68]
#define SB_CST    203776      // f32 [16][68]
#define SB_TAB    208128      // float4 [23*16]
#define SB_BIAS   214016      // float4 [16]
#define SB_TOK    214272      // int [64]
#define SMEM_BYTES 214528

static __device__ __align__(128) __nv_bfloat16 g_hbf[(size_t)LAYERS * T * 2 * 16384];
static __device__ float g_hseq7[(size_t)T * H * B];
static __device__ float g_table[VOCAB * G];
static __device__ int   g_done[LAYERS * T];

// ---------- helpers ----------
__device__ __forceinline__ uint32_t smem_u32(const void* p) {
    uint32_t a;
    asm("{ .reg .u64 t; cvta.to.shared.u64 t, %1; cvt.u32.u64 %0, t; }" : "=r"(a) : "l"(p));
    return a;
}
__device__ __forceinline__ float tanha(float x) {
    float y; asm("tanh.approx.f32 %0, %1;" : "=f"(y) : "f"(x));
    return y;
}
__device__ __forceinline__ float sigm(float x) { return fmaf(0.5f, tanha(0.5f * x), 0.5f); }

__device__ __forceinline__ void wait_done(int idx) {
    if (threadIdx.x == 0) {
        volatile int* p = &g_done[idx];
        while (*p < NC) __nanosleep(32);
    }
    __syncthreads();
}

#define LDSM4(r0,r1,r2,r3,addr) \
    asm volatile("ldmatrix.sync.aligned.m8n8.x4.shared.b16 {%0,%1,%2,%3}, [%4];" \
                 : "=r"(r0),"=r"(r1),"=r"(r2),"=r"(r3) : "r"(addr))

#define MMA16816(c, a0,a1,a2,a3, b0,b1) \
    asm volatile("mma.sync.aligned.m16n8k16.row.col.f32.bf16.bf16.f32 " \
                 "{%0,%1,%2,%3},{%4,%5,%6,%7},{%8,%9},{%0,%1,%2,%3};" \
                 : "+f"((c)[0]),"+f"((c)[1]),"+f"((c)[2]),"+f"((c)[3]) \
                 : "r"(a0),"r"(a1),"r"(a2),"r"(a3),"r"(b0),"r"(b1))

// Load this warp's persisted A fragments (8 k16 x 8 regs) from a padded smem plane.
__device__ __forceinline__ void load_wfrags(uint32_t (&wa)[8][8], uint32_t planeP, uint32_t ar) {
#pragma unroll
    for (int k = 0; k < 8; ++k) {
        LDSM4(wa[k][0],wa[k][1],wa[k][2],wa[k][3], planeP + ar + k * 32);
        LDSM4(wa[k][4],wa[k][5],wa[k][6],wa[k][7], planeP + ar + 16 * WSTR + k * 32);
    }
}

// B_hi phase: acc += A_hi(regs)*B + A_lo(smem)*B over 8 k16 chunks.
__device__ __forceinline__ void phase_bhi(
    const uint32_t (&wa)[8][8], uint32_t aLoP, uint32_t bufP,
    float (&acc)[2][4][4], uint32_t ar, uint32_t br)
{
    const uint32_t aLo = aLoP + ar, bP = bufP + br;
    uint32_t fal[2][8], fb[2][8];
    LDSM4(fal[0][0],fal[0][1],fal[0][2],fal[0][3], aLo);
    LDSM4(fal[0][4],fal[0][5],fal[0][6],fal[0][7], aLo + 16 * WSTR);
    LDSM4(fb[0][0],fb[0][1],fb[0][2],fb[0][3], bP);
    LDSM4(fb[0][4],fb[0][5],fb[0][6],fb[0][7], bP + 16 * WSTR);
#pragma unroll
    for (int k = 0; k < 8; ++k) {
        const int cur = k & 1;
        if (k < 7) {
            const int nx = cur ^ 1;
            LDSM4(fal[nx][0],fal[nx][1],fal[nx][2],fal[nx][3], aLo + (k+1)*32);
            LDSM4(fal[nx][4],fal[nx][5],fal[nx][6],fal[nx][7], aLo + 16*WSTR + (k+1)*32);
            LDSM4(fb[nx][0],fb[nx][1],fb[nx][2],fb[nx][3], bP + (k+1)*32);
            LDSM4(fb[nx][4],fb[nx][5],fb[nx][6],fb[nx][7], bP + 16*WSTR + (k+1)*32);
        }
#pragma unroll
        for (int mh = 0; mh < 2; ++mh) {
            const uint32_t* ah = &wa[k][mh * 4];
            const uint32_t* al = &fal[cur][mh * 4];
            const uint32_t* b  = fb[cur];
            MMA16816(acc[mh][0], ah[0],ah[1],ah[2],ah[3], b[0],b[2]);
            MMA16816(acc[mh][1], ah[0],ah[1],ah[2],ah[3], b[1],b[3]);
            MMA16816(acc[mh][2], ah[0],ah[1],ah[2],ah[3], b[4],b[6]);
            MMA16816(acc[mh][3], ah[0],ah[1],ah[2],ah[3], b[5],b[7]);
            MMA16816(acc[mh][0], al[0],al[1],al[2],al[3], b[0],b[2]);
            MMA16816(acc[mh][1], al[0],al[1],al[2],al[3], b[1],b[3]);
            MMA16816(acc[mh][2], al[0],al[1],al[2],al[3], b[4],b[6]);
            MMA16816(acc[mh][3], al[0],al[1],al[2],al[3], b[5],b[7]);
        }
    }
}

// B_lo phase: acc += A_hi(regs)*B_lo over 8 k16 chunks.
__device__ __forceinline__ void phase_blo(
    const uint32_t (&wa)[8][8], uint32_t bufP, float (&acc)[2][4][4], uint32_t br)
{
    const uint32_t bP = bufP + br;
    uint32_t fb[2][8];
    LDSM4(fb[0][0],fb[0][1],fb[0][2],fb[0][3], bP);
    LDSM4(fb[0][4],fb[0][5],fb[0][6],fb[0][7], bP + 16 * WSTR);
#pragma unroll
    for (int k = 0; k < 8; ++k) {
        const int cur = k & 1;
        if (k < 7) {
            const int nx = cur ^ 1;
            LDSM4(fb[nx][0],fb[nx][1],fb[nx][2],fb[nx][3], bP + (k+1)*32);
            LDSM4(fb[nx][4],fb[nx][5],fb[nx][6],fb[nx][7], bP + 16*WSTR + (k+1)*32);
        }
#pragma unroll
        for (int mh = 0; mh < 2; ++mh) {
            const uint32_t* ah = &wa[k][mh * 4];
            const uint32_t* b  = fb[cur];
            MMA16816(acc[mh][0], ah[0],ah[1],ah[2],ah[3], b[0],b[2]);
            MMA16816(acc[mh][1], ah[0],ah[1],ah[2],ah[3], b[1],b[3]);
            MMA16816(acc[mh][2], ah[0],ah[1],ah[2],ah[3], b[4],b[6]);
            MMA16816(acc[mh][3], ah[0],ah[1],ah[2],ah[3], b[5],b[7]);
        }
    }
}

// async-stage one dense 32KB global plane into a padded smem plane; commits a group.
__device__ __forceinline__ void stage(uint32_t dstS, const char* src, int tid) {
#pragma unroll
    for (int u = 0; u < 8; ++u) {
        int i = tid + u * THR;
        int b = i >> 5, kc = i & 31;
        asm volatile("cp.async.cg.shared.global [%0], [%1], 16;"
                     :: "r"(dstS + (uint32_t)(b * WSTR + kc * 16)),
                        "l"(src + b * 512 + kc * 16) : "memory");
    }
    asm volatile("cp.async.commit_group;" ::: "memory");
}
#define CP_WAIT2() asm volatile("cp.async.wait_group 2;" ::: "memory")
#define CP_WAIT1() asm volatile("cp.async.wait_group 1;" ::: "memory")
#define CP_WAIT0() asm volatile("cp.async.wait_group 0;" ::: "memory")

// ---------- prelude ----------
__global__ void zero_done_kernel() {
    int i = blockIdx.x * blockDim.x + threadIdx.x;
    if (i < LAYERS * T) g_done[i] = 0;
}
__global__ void build_table_kernel(const float* __restrict__ emb, const float* __restrict__ Wih0,
                                   const float* __restrict__ bih, const float* __restrict__ bhh) {
    int idx = blockIdx.x * blockDim.x + threadIdx.x;
    if (idx >= VOCAB * G) return;
    int v = idx / G, j = idx % G;
    float s = bih[j] + bhh[j];
#pragma unroll
    for (int e = 0; e < EMB; ++e) s += emb[v * EMB + e] * Wih0[j * EMB + e];
    g_table[idx] = s;
}

// ---------- main persistent wavefront kernel ----------
extern "C" __global__ void __launch_bounds__(THR, 1)
lstm_main_kernel(const int* __restrict__ x,
                 const float* __restrict__ Wih_rest,
                 const float* __restrict__ Whh,
                 const float* __restrict__ bih,
                 const float* __restrict__ bhh)
{
    extern __shared__ char smem[];
    const uint32_t sb = smem_u32(smem);
    const int tid  = threadIdx.x;
    const int warp = tid >> 5, lane = tid & 31;
    const int l = blockIdx.x >> 4;
    const int c = blockIdx.x & 15;          // unit block: units c*16 .. c*16+15
    const int kh = warp >> 2, mi = (warp >> 1) & 1, ni = warp & 1;

    float*  gx    = (float*)(smem + SB_GX);     // [64][68]
    float*  gx2   = (float*)(smem + SB_GX2);    // [64][68]
    float*  cst   = (float*)(smem + SB_CST);    // [16][68]
    float4* tab4  = (float4*)(smem + SB_TAB);
    float4* bias4 = (float4*)(smem + SB_BIAS);
    int*    tokI  = (int*)(smem + SB_TOK);

    // per-warp fragment base offsets
    const uint32_t kOff = (uint32_t)(kh * 256) + ((lane >> 4) << 4);
    const uint32_t ar = (uint32_t)(mi * 32 + (lane & 15)) * WSTR + kOff;
    const uint32_t br = (uint32_t)(ni * 32 + (lane & 15)) * WSTR + kOff;

    // ---- weight prep: hi planes -> BUF0/BUF1 (transient), lo planes resident ----
    {
        const float* Wl = Whh + (size_t)l * G * H;
        for (int idx = tid; idx < 64 * 256; idx += THR) {
            int r = idx >> 8, k = idx & 255;
            int jg = (r >> 4) * H + c * 16 + (r & 15);
            float w = Wl[(size_t)jg * H + k];
            __nv_bfloat16 wh = __float2bfloat16(w);
            *(__nv_bfloat16*)(smem + SB_BUF0 + r * WSTR + k * 2) = wh;
            *(__nv_bfloat16*)(smem + SB_WHH_LO + r * WSTR + k * 2) =
                __float2bfloat16(w - __bfloat162float(wh));
        }
    }
    if (l > 0) {
        const float* Wl = Wih_rest + (size_t)(l - 1) * G * H;
        for (int idx = tid; idx < 64 * 256; idx += THR) {
            int r = idx >> 8, k = idx & 255;
            int jg = (r >> 4) * H + c * 16 + (r & 15);
            float w = Wl[(size_t)jg * H + k];
            __nv_bfloat16 wh = __float2bfloat16(w);
            *(__nv_bfloat16*)(smem + SB_BUF1 + r * WSTR + k * 2) = wh;
            *(__nv_bfloat16*)(smem + SB_WIH_LO + r * WSTR + k * 2) =
                __float2bfloat16(w - __bfloat162float(wh));
        }
        if (tid < 16) {
            int u = tid;
            float4 q;
            q.x = bih[l * G + 0 * H + c * 16 + u] + bhh[l * G + 0 * H + c * 16 + u];
            q.y = bih[l * G + 1 * H + c * 16 + u] + bhh[l * G + 1 * H + c * 16 + u];
            q.z = bih[l * G + 2 * H + c * 16 + u] + bhh[l * G + 2 * H + c * 16 + u];
            q.w = bih[l * G + 3 * H + c * 16 + u] + bhh[l * G + 3 * H + c * 16 + u];
            bias4[u] = q;
        }
    } else {
        for (int idx = tid; idx < VOCAB * 16; idx += THR) {
            int v = idx >> 4, u = idx & 15;
            float4 q;
            q.x = g_table[v * G + 0 * H + c * 16 + u];
            q.y = g_table[v * G + 1 * H + c * 16 + u];
            q.z = g_table[v * G + 2 * H + c * 16 + u];
            q.w = g_table[v * G + 3 * H + c * 16 + u];
            tab4[idx] = q;
        }
    }
    __syncthreads();

    // ---- persist W_hi fragments in registers for the whole run ----
    uint32_t whh_hi[8][8], wih_hi[8][8];
    load_wfrags(whh_hi, sb + SB_BUF0, ar);
    if (l > 0) load_wfrags(wih_hi, sb + SB_BUF1, ar);
    else {
#pragma unroll
        for (int k = 0; k < 8; ++k)
#pragma unroll
            for (int j = 0; j < 8; ++j) wih_hi[k][j] = 0;
    }
    __syncthreads();   // BUF0/BUF1 free for staging

    for (int t = 0; t < T; ++t) {
        if (l == 0 && tid < 64) tokI[tid] = x[tid * T + t];

        float acc[2][4][4];
#pragma unroll
        for (int a = 0; a < 2; ++a)
#pragma unroll
            for (int b = 0; b < 4; ++b)
#pragma unroll
                for (int q = 0; q < 4; ++q) acc[a][b][q] = 0.f;

        const bool rec = (t > 0), inp = (l > 0);
        const char* recsrc = (const char*)g_hbf + (size_t)(l * T + t - 1) * 65536;
        const char* insrc  = (const char*)g_hbf + (size_t)((l - 1) * T + t) * 65536;

        if (rec && inp) {
            wait_done(l * T + (t - 1));
            stage(sb + SB_BUF0, recsrc, tid);                 // G1 rec_hi
            stage(sb + SB_BUF1, recsrc + 32768, tid);         // G2 rec_lo
            wait_done((l - 1) * T + t);
            stage(sb + SB_BUF2, insrc, tid);                  // G3 in_hi
            CP_WAIT2(); __syncthreads();                      // buf0 ready
            phase_bhi(whh_hi, sb + SB_WHH_LO, sb + SB_BUF0, acc, ar, br);
            CP_WAIT1(); __syncthreads();                      // buf1 ready; buf0 reads done
            stage(sb + SB_BUF0, insrc + 32768, tid);          // G4 in_lo (overlaps)
            phase_blo(whh_hi, sb + SB_BUF1, acc, br);
            CP_WAIT1(); __syncthreads();                      // buf2 ready (G4 may pend)
            phase_bhi(wih_hi, sb + SB_WIH_LO, sb + SB_BUF2, acc, ar, br);
            CP_WAIT0(); __syncthreads();                      // buf0 = in_lo ready
            phase_blo(wih_hi, sb + SB_BUF0, acc, br);
        } else if (rec) {
            wait_done(l * T + (t - 1));
            stage(sb + SB_BUF0, recsrc, tid);
            stage(sb + SB_BUF1, recsrc + 32768, tid);
            CP_WAIT1(); __syncthreads();
            phase_bhi(whh_hi, sb + SB_WHH_LO, sb + SB_BUF0, acc, ar, br);
            CP_WAIT0(); __syncthreads();
            phase_blo(whh_hi, sb + SB_BUF1, acc, br);
        } else if (inp) {
            wait_done((l - 1) * T + t);
            stage(sb + SB_BUF0, insrc, tid);
            stage(sb + SB_BUF1, insrc + 32768, tid);
            CP_WAIT1(); __syncthreads();
            phase_bhi(wih_hi, sb + SB_WIH_LO, sb + SB_BUF0, acc, ar, br);
            CP_WAIT0(); __syncthreads();
            phase_blo(wih_hi, sb + SB_BUF1, acc, br);
        }

        // ---- split-K: kh=0 -> gx, kh=1 -> gx2 (gx no longer aliases staging) ----
        {
            float* dst = (kh == 0) ? gx : gx2;
#pragma unroll
            for (int ms = 0; ms < 2; ++ms) {
                int m = mi * 32 + ms * 16 + (lane >> 2);
#pragma unroll
                for (int ns = 0; ns < 4; ++ns) {
                    int b = ni * 32 + ns * 8 + (lane & 3) * 2;
                    *(float2*)(dst + m * 68 + b)       = make_float2(acc[ms][ns][0], acc[ms][ns][1]);
                    *(float2*)(dst + (m + 8) * 68 + b) = make_float2(acc[ms][ns][2], acc[ms][ns][3]);
                }
            }
        }
        __syncthreads();

        // ---- cell update: thread = (u, 4 b's); coalesced bf16 h publish ----
        {
            const int u = tid & 15, grp = tid >> 4;
            char* dstP = (char*)g_hbf + (size_t)(l * T + t) * 65536;
            const int k = c * 16 + u;
            float4 bq = (l > 0) ? bias4[u] : make_float4(0.f, 0.f, 0.f, 0.f);
#pragma unroll
            for (int i = 0; i < 4; ++i) {
                int b = grp * 4 + i;
                float4 q = (l == 0) ? tab4[tokI[b] * 16 + u] : bq;
                float ig = gx[(0 * 16 + u) * 68 + b] + gx2[(0 * 16 + u) * 68 + b] + q.x;
                float fg = gx[(1 * 16 + u) * 68 + b] + gx2[(1 * 16 + u) * 68 + b] + q.y;
                float gg = gx[(2 * 16 + u) * 68 + b] + gx2[(2 * 16 + u) * 68 + b] + q.z;
                float og = gx[(3 * 16 + u) * 68 + b] + gx2[(3 * 16 + u) * 68 + b] + q.w;
                float cv = (t == 0) ? 0.f : cst[u * 68 + b];
                float cn = sigm(fg) * cv + sigm(ig) * tanha(gg);
                cst[u * 68 + b] = cn;
                float hv = sigm(og) * tanha(cn);
                __nv_bfloat16 hh = __float2bfloat16(hv);
                __nv_bfloat16 hl = __float2bfloat16(hv - __bfloat162float(hh));
                *(__nv_bfloat16*)(dstP + b * 512 + k * 2)         = hh;
                *(__nv_bfloat16*)(dstP + 32768 + b * 512 + k * 2) = hl;
                if (l == 7) g_hseq7[(size_t)t * 16384 + k * 64 + b] = hv;
            }
        }
        __threadfence();
        __syncthreads();
        if (tid == 0) atomicAdd(&g_done[l * T + t], 1);
    }
}

// ---------- final FC ----------
#define FC_SMEM_FLOATS (256 * 64 + 256 * 24 + 32)
__global__ void __launch_bounds__(256)
fc_kernel(const float* __restrict__ fcw, const float* __restrict__ fcb,
          float* __restrict__ out)
{
    extern __shared__ float fsm[];
    float* hs = fsm;
    float* ws = fsm + 256 * 64;
    float* bs = ws + 256 * 24;
    const int tid = threadIdx.x, t = blockIdx.x;

    const float* h7 = g_hseq7 + (size_t)t * H * B;
    {
        const float4* s = (const float4*)h7;
        float4* d = (float4*)hs;
        for (int i = tid; i < 4096; i += 256) d[i] = s[i];
    }
    for (int i = tid; i < VOCAB * H; i += 256) {
        int v = i >> 8, k = i & 255;
        ws[k * 24 + v] = fcw[i];
    }
    if (tid < VOCAB) bs[tid] = fcb[tid];
    __syncthreads();

    const int b = tid & 63, vg = tid >> 6;
    const int v0 = vg * 6;
    const int nv = (v0 + 6 <= VOCAB) ? 6 : (VOCAB - v0);
    float acc[6] = {0.f, 0.f, 0.f, 0.f, 0.f, 0.f};
#pragma unroll 4
    for (int k = 0; k < 256; ++k) {
        float a = hs[k * 64 + b];
#pragma unroll
        for (int j = 0; j < 6; ++j) acc[j] += a * ws[k * 24 + v0 + j];
    }
    for (int j = 0; j < nv; ++j)
        out[((size_t)b * T + t) * VOCAB + v0 + j] = acc[j] + bs[v0 + j];
}

// ---------- launch ----------
extern "C" void kernel_launch(void* const* d_in, const int* in_sizes, int n_in,
                              void* d_out, int out_size)
{
    const int*   x        = (const int*)d_in[0];
    const float* emb      = (const float*)d_in[1];
    const float* Wih0     = (const float*)d_in[2];
    const float* Wih_rest = (const float*)d_in[3];
    const float* Whh      = (const float*)d_in[4];
    const float* bih      = (const float*)d_in[5];
    const float* bhh      = (const float*)d_in[6];
    const float* fcw      = (const float*)d_in[7];
    const float* fcb      = (const float*)d_in[8];
    float*       out      = (float*)d_out;

    cudaFuncSetAttribute(lstm_main_kernel,
                         cudaFuncAttributeMaxDynamicSharedMemorySize, SMEM_BYTES);
    cudaFuncSetAttribute(fc_kernel,
                         cudaFuncAttributeMaxDynamicSharedMemorySize, FC_SMEM_FLOATS * 4);

    zero_done_kernel<<<16, 256>>>();
    build_table_kernel<<<(VOCAB * G + 255) / 256, 256>>>(emb, Wih0, bih, bhh);
    lstm_main_kernel<<<LAYERS * NC, THR, SMEM_BYTES>>>(x, Wih_rest, Whh, bih, bhh);
    fc_kernel<<<T, 256, FC_SMEM_FLOATS * 4>>>(fcw, fcb, out);
}

// round 14
// speedup vs baseline: 3.8102x; 1.2355x over previous
#include <cuda_runtime.h>
#include <cuda_fp16.h>
#include <cstdint>

#define LAYERS 8
#define T      512
#define B      64
#define H      256
#define G      1024
#define VOCAB  23
#define EMB    16
#define NC     16
#define THR    256

#define WSTR   528            // bytes per padded row (264 fp16)

// smem byte offsets (no aliasing)
#define SB_WHH_LO 0
#define SB_WIH_LO 33792
#define SB_BUF0   67584
#define SB_BUF1   101376
#define SB_GX     135168      // f32 [64][68]
#define SB_GX2    152576      // f32 [64][68]
#define SB_CST    169984      // f32 [16][68]
#define SB_TAB    174336      // float4 [23*16]
#define SB_BIAS   180224      // float4 [16]
#define SB_TOK    180480      // int [64]
#define SMEM_BYTES 180736

static __device__ __align__(128) __half g_hbf[(size_t)LAYERS * T * 16384];   // [l][t][b][k] fp16
static __device__ float g_hseq7[(size_t)T * H * B];
static __device__ float g_table[VOCAB * G];
static __device__ int   g_done[LAYERS * T];

// ---------- helpers ----------
__device__ __forceinline__ uint32_t smem_u32(const void* p) {
    uint32_t a;
    asm("{ .reg .u64 t; cvta.to.shared.u64 t, %1; cvt.u32.u64 %0, t; }" : "=r"(a) : "l"(p));
    return a;
}
__device__ __forceinline__ float tanha(float x) {
    float y; asm("tanh.approx.f32 %0, %1;" : "=f"(y) : "f"(x));
    return y;
}
__device__ __forceinline__ float sigm(float x) { return fmaf(0.5f, tanha(0.5f * x), 0.5f); }

__device__ __forceinline__ void wait_done(int idx) {
    if (threadIdx.x == 0) {
        volatile int* p = &g_done[idx];
        while (*p < NC) __nanosleep(32);
    }
    __syncthreads();
}

#define LDSM4(r0,r1,r2,r3,addr) \
    asm volatile("ldmatrix.sync.aligned.m8n8.x4.shared.b16 {%0,%1,%2,%3}, [%4];" \
                 : "=r"(r0),"=r"(r1),"=r"(r2),"=r"(r3) : "r"(addr))

#define MMA16816(c, a0,a1,a2,a3, b0,b1) \
    asm volatile("mma.sync.aligned.m16n8k16.row.col.f32.f16.f16.f32 " \
                 "{%0,%1,%2,%3},{%4,%5,%6,%7},{%8,%9},{%0,%1,%2,%3};" \
                 : "+f"((c)[0]),"+f"((c)[1]),"+f"((c)[2]),"+f"((c)[3]) \
                 : "r"(a0),"r"(a1),"r"(a2),"r"(a3),"r"(b0),"r"(b1))

// Load this warp's persisted W_hi fragments (8 k16 x 8 regs) from a padded smem plane.
__device__ __forceinline__ void load_wfrags(uint32_t (&wa)[8][8], uint32_t planeP, uint32_t ar) {
#pragma unroll
    for (int k = 0; k < 8; ++k) {
        LDSM4(wa[k][0],wa[k][1],wa[k][2],wa[k][3], planeP + ar + k * 32);
        LDSM4(wa[k][4],wa[k][5],wa[k][6],wa[k][7], planeP + ar + 16 * WSTR + k * 32);
    }
}

// One pass: acc += W_hi(regs)*B + W_lo(smem)*B over 8 k16 chunks; B fragments shared.
__device__ __forceinline__ void pass(
    const uint32_t (&wa)[8][8], uint32_t aLoP, uint32_t bufP,
    float (&acc)[2][4][4], uint32_t ar, uint32_t br)
{
    const uint32_t aLo = aLoP + ar, bP = bufP + br;
    uint32_t fal[2][8], fb[2][8];
    LDSM4(fal[0][0],fal[0][1],fal[0][2],fal[0][3], aLo);
    LDSM4(fal[0][4],fal[0][5],fal[0][6],fal[0][7], aLo + 16 * WSTR);
    LDSM4(fb[0][0],fb[0][1],fb[0][2],fb[0][3], bP);
    LDSM4(fb[0][4],fb[0][5],fb[0][6],fb[0][7], bP + 16 * WSTR);
#pragma unroll
    for (int k = 0; k < 8; ++k) {
        const int cur = k & 1;
        if (k < 7) {
            const int nx = cur ^ 1;
            LDSM4(fal[nx][0],fal[nx][1],fal[nx][2],fal[nx][3], aLo + (k+1)*32);
            LDSM4(fal[nx][4],fal[nx][5],fal[nx][6],fal[nx][7], aLo + 16*WSTR + (k+1)*32);
            LDSM4(fb[nx][0],fb[nx][1],fb[nx][2],fb[nx][3], bP + (k+1)*32);
            LDSM4(fb[nx][4],fb[nx][5],fb[nx][6],fb[nx][7], bP + 16*WSTR + (k+1)*32);
        }
#pragma unroll
        for (int mh = 0; mh < 2; ++mh) {
            const uint32_t* ah = &wa[k][mh * 4];
            const uint32_t* al = &fal[cur][mh * 4];
            const uint32_t* b  = fb[cur];
            MMA16816(acc[mh][0], ah[0],ah[1],ah[2],ah[3], b[0],b[2]);
            MMA16816(acc[mh][1], ah[0],ah[1],ah[2],ah[3], b[1],b[3]);
            MMA16816(acc[mh][2], ah[0],ah[1],ah[2],ah[3], b[4],b[6]);
            MMA16816(acc[mh][3], ah[0],ah[1],ah[2],ah[3], b[5],b[7]);
            MMA16816(acc[mh][0], al[0],al[1],al[2],al[3], b[0],b[2]);
            MMA16816(acc[mh][1], al[0],al[1],al[2],al[3], b[1],b[3]);
            MMA16816(acc[mh][2], al[0],al[1],al[2],al[3], b[4],b[6]);
            MMA16816(acc[mh][3], al[0],al[1],al[2],al[3], b[5],b[7]);
        }
    }
}

// async-stage one dense 32KB global plane into a padded smem plane; commits a group.
__device__ __forceinline__ void stage(uint32_t dstS, const char* src, int tid) {
#pragma unroll
    for (int u = 0; u < 8; ++u) {
        int i = tid + u * THR;
        int b = i >> 5, kc = i & 31;
        asm volatile("cp.async.cg.shared.global [%0], [%1], 16;"
                     :: "r"(dstS + (uint32_t)(b * WSTR + kc * 16)),
                        "l"(src + b * 512 + kc * 16) : "memory");
    }
    asm volatile("cp.async.commit_group;" ::: "memory");
}
#define CP_WAIT1() asm volatile("cp.async.wait_group 1;" ::: "memory")
#define CP_WAIT0() asm volatile("cp.async.wait_group 0;" ::: "memory")

// ---------- prelude ----------
__global__ void zero_done_kernel() {
    int i = blockIdx.x * blockDim.x + threadIdx.x;
    if (i < LAYERS * T) g_done[i] = 0;
}
__global__ void build_table_kernel(const float* __restrict__ emb, const float* __restrict__ Wih0,
                                   const float* __restrict__ bih, const float* __restrict__ bhh) {
    int idx = blockIdx.x * blockDim.x + threadIdx.x;
    if (idx >= VOCAB * G) return;
    int v = idx / G, j = idx % G;
    float s = bih[j] + bhh[j];
#pragma unroll
    for (int e = 0; e < EMB; ++e) s += emb[v * EMB + e] * Wih0[j * EMB + e];
    g_table[idx] = s;
}

// ---------- main persistent wavefront kernel ----------
extern "C" __global__ void __launch_bounds__(THR, 1)
lstm_main_kernel(const int* __restrict__ x,
                 const float* __restrict__ Wih_rest,
                 const float* __restrict__ Whh,
                 const float* __restrict__ bih,
                 const float* __restrict__ bhh)
{
    extern __shared__ char smem[];
    const uint32_t sb = smem_u32(smem);
    const int tid  = threadIdx.x;
    const int warp = tid >> 5, lane = tid & 31;
    const int l = blockIdx.x >> 4;
    const int c = blockIdx.x & 15;          // unit block: units c*16 .. c*16+15
    const int kh = warp >> 2, mi = (warp >> 1) & 1, ni = warp & 1;

    float*  gx    = (float*)(smem + SB_GX);     // [64][68]
    float*  gx2   = (float*)(smem + SB_GX2);    // [64][68]
    float*  cst   = (float*)(smem + SB_CST);    // [16][68]
    float4* tab4  = (float4*)(smem + SB_TAB);
    float4* bias4 = (float4*)(smem + SB_BIAS);
    int*    tokI  = (int*)(smem + SB_TOK);

    // per-warp fragment base offsets
    const uint32_t kOff = (uint32_t)(kh * 256) + ((lane >> 4) << 4);
    const uint32_t ar = (uint32_t)(mi * 32 + (lane & 15)) * WSTR + kOff;
    const uint32_t br = (uint32_t)(ni * 32 + (lane & 15)) * WSTR + kOff;

    // ---- weight prep: fp16 hi -> BUF0/BUF1 (transient), fp16 lo resident ----
    {
        const float* Wl = Whh + (size_t)l * G * H;
        for (int idx = tid; idx < 64 * 256; idx += THR) {
            int r = idx >> 8, k = idx & 255;
            int jg = (r >> 4) * H + c * 16 + (r & 15);
            float w = Wl[(size_t)jg * H + k];
            __half wh = __float2half_rn(w);
            *(__half*)(smem + SB_BUF0 + r * WSTR + k * 2) = wh;
            *(__half*)(smem + SB_WHH_LO + r * WSTR + k * 2) =
                __float2half_rn(w - __half2float(wh));
        }
    }
    if (l > 0) {
        const float* Wl = Wih_rest + (size_t)(l - 1) * G * H;
        for (int idx = tid; idx < 64 * 256; idx += THR) {
            int r = idx >> 8, k = idx & 255;
            int jg = (r >> 4) * H + c * 16 + (r & 15);
            float w = Wl[(size_t)jg * H + k];
            __half wh = __float2half_rn(w);
            *(__half*)(smem + SB_BUF1 + r * WSTR + k * 2) = wh;
            *(__half*)(smem + SB_WIH_LO + r * WSTR + k * 2) =
                __float2half_rn(w - __half2float(wh));
        }
        if (tid < 16) {
            int u = tid;
            float4 q;
            q.x = bih[l * G + 0 * H + c * 16 + u] + bhh[l * G + 0 * H + c * 16 + u];
            q.y = bih[l * G + 1 * H + c * 16 + u] + bhh[l * G + 1 * H + c * 16 + u];
            q.z = bih[l * G + 2 * H + c * 16 + u] + bhh[l * G + 2 * H + c * 16 + u];
            q.w = bih[l * G + 3 * H + c * 16 + u] + bhh[l * G + 3 * H + c * 16 + u];
            bias4[u] = q;
        }
    } else {
        for (int idx = tid; idx < VOCAB * 16; idx += THR) {
            int v = idx >> 4, u = idx & 15;
            float4 q;
            q.x = g_table[v * G + 0 * H + c * 16 + u];
            q.y = g_table[v * G + 1 * H + c * 16 + u];
            q.z = g_table[v * G + 2 * H + c * 16 + u];
            q.w = g_table[v * G + 3 * H + c * 16 + u];
            tab4[idx] = q;
        }
    }
    __syncthreads();

    // ---- persist W_hi fragments in registers for the whole run ----
    uint32_t whh_hi[8][8], wih_hi[8][8];
    load_wfrags(whh_hi, sb + SB_BUF0, ar);
    if (l > 0) load_wfrags(wih_hi, sb + SB_BUF1, ar);
    else {
#pragma unroll
        for (int k = 0; k < 8; ++k)
#pragma unroll
            for (int j = 0; j < 8; ++j) wih_hi[k][j] = 0;
    }
    __syncthreads();   // BUF0/BUF1 free for staging

    for (int t = 0; t < T; ++t) {
        if (l == 0 && tid < 64) tokI[tid] = x[tid * T + t];

        float acc[2][4][4];
#pragma unroll
        for (int a = 0; a < 2; ++a)
#pragma unroll
            for (int b = 0; b < 4; ++b)
#pragma unroll
                for (int q = 0; q < 4; ++q) acc[a][b][q] = 0.f;

        const bool rec = (t > 0), inp = (l > 0);
        const char* recsrc = (const char*)g_hbf + (size_t)(l * T + t - 1) * 32768;
        const char* insrc  = (const char*)g_hbf + (size_t)((l - 1) * T + t) * 32768;

        if (rec && inp) {
            wait_done(l * T + (t - 1));
            stage(sb + SB_BUF0, recsrc, tid);                 // G1 rec_h
            wait_done((l - 1) * T + t);
            stage(sb + SB_BUF1, insrc, tid);                  // G2 in_h
            CP_WAIT1(); __syncthreads();                      // buf0 ready
            pass(whh_hi, sb + SB_WHH_LO, sb + SB_BUF0, acc, ar, br);
            CP_WAIT0(); __syncthreads();                      // buf1 ready
            pass(wih_hi, sb + SB_WIH_LO, sb + SB_BUF1, acc, ar, br);
        } else if (rec) {
            wait_done(l * T + (t - 1));
            stage(sb + SB_BUF0, recsrc, tid);
            CP_WAIT0(); __syncthreads();
            pass(whh_hi, sb + SB_WHH_LO, sb + SB_BUF0, acc, ar, br);
        } else if (inp) {
            wait_done((l - 1) * T + t);
            stage(sb + SB_BUF0, insrc, tid);
            CP_WAIT0(); __syncthreads();
            pass(wih_hi, sb + SB_WIH_LO, sb + SB_BUF0, acc, ar, br);
        }
        __syncthreads();   // pass reads of BUFs done before next-step staging

        // ---- split-K: kh=0 -> gx, kh=1 -> gx2 ----
        {
            float* dst = (kh == 0) ? gx : gx2;
#pragma unroll
            for (int ms = 0; ms < 2; ++ms) {
                int m = mi * 32 + ms * 16 + (lane >> 2);
#pragma unroll
                for (int ns = 0; ns < 4; ++ns) {
                    int b = ni * 32 + ns * 8 + (lane & 3) * 2;
                    *(float2*)(dst + m * 68 + b)       = make_float2(acc[ms][ns][0], acc[ms][ns][1]);
                    *(float2*)(dst + (m + 8) * 68 + b) = make_float2(acc[ms][ns][2], acc[ms][ns][3]);
                }
            }
        }
        __syncthreads();

        // ---- cell update: thread = (u, 4 b's); coalesced fp16 h publish ----
        {
            const int u = tid & 15, grp = tid >> 4;
            char* dstP = (char*)g_hbf + (size_t)(l * T + t) * 32768;
            const int k = c * 16 + u;
            float4 bq = (l > 0) ? bias4[u] : make_float4(0.f, 0.f, 0.f, 0.f);
#pragma unroll
            for (int i = 0; i < 4; ++i) {
                int b = grp * 4 + i;
                float4 q = (l == 0) ? tab4[tokI[b] * 16 + u] : bq;
                float ig = gx[(0 * 16 + u) * 68 + b] + gx2[(0 * 16 + u) * 68 + b] + q.x;
                float fg = gx[(1 * 16 + u) * 68 + b] + gx2[(1 * 16 + u) * 68 + b] + q.y;
                float gg = gx[(2 * 16 + u) * 68 + b] + gx2[(2 * 16 + u) * 68 + b] + q.z;
                float og = gx[(3 * 16 + u) * 68 + b] + gx2[(3 * 16 + u) * 68 + b] + q.w;
                float cv = (t == 0) ? 0.f : cst[u * 68 + b];
                float cn = sigm(fg) * cv + sigm(ig) * tanha(gg);
                cst[u * 68 + b] = cn;
                float hv = sigm(og) * tanha(cn);
                *(__half*)(dstP + b * 512 + k * 2) = __float2half_rn(hv);
                if (l == 7) g_hseq7[(size_t)t * 16384 + k * 64 + b] = hv;
            }
        }
        __threadfence();
        __syncthreads();
        if (tid == 0) atomicAdd(&g_done[l * T + t], 1);
    }
}

// ---------- final FC ----------
#define FC_SMEM_FLOATS (256 * 64 + 256 * 24 + 32)
__global__ void __launch_bounds__(256)
fc_kernel(const float* __restrict__ fcw, const float* __restrict__ fcb,
          float* __restrict__ out)
{
    extern __shared__ float fsm[];
    float* hs = fsm;
    float* ws = fsm + 256 * 64;
    float* bs = ws + 256 * 24;
    const int tid = threadIdx.x, t = blockIdx.x;

    const float* h7 = g_hseq7 + (size_t)t * H * B;
    {
        const float4* s = (const float4*)h7;
        float4* d = (float4*)hs;
        for (int i = tid; i < 4096; i += 256) d[i] = s[i];
    }
    for (int i = tid; i < VOCAB * H; i += 256) {
        int v = i >> 8, k = i & 255;
        ws[k * 24 + v] = fcw[i];
    }
    if (tid < VOCAB) bs[tid] = fcb[tid];
    __syncthreads();

    const int b = tid & 63, vg = tid >> 6;
    const int v0 = vg * 6;
    const int nv = (v0 + 6 <= VOCAB) ? 6 : (VOCAB - v0);
    float acc[6] = {0.f, 0.f, 0.f, 0.f, 0.f, 0.f};
#pragma unroll 4
    for (int k = 0; k < 256; ++k) {
        float a = hs[k * 64 + b];
#pragma unroll
        for (int j = 0; j < 6; ++j) acc[j] += a * ws[k * 24 + v0 + j];
    }
    for (int j = 0; j < nv; ++j)
        out[((size_t)b * T + t) * VOCAB + v0 + j] = acc[j] + bs[v0 + j];
}

// ---------- launch ----------
extern "C" void kernel_launch(void* const* d_in, const int* in_sizes, int n_in,
                              void* d_out, int out_size)
{
    const int*   x        = (const int*)d_in[0];
    const float* emb      = (const float*)d_in[1];
    const float* Wih0     = (const float*)d_in[2];
    const float* Wih_rest = (const float*)d_in[3];
    const float* Whh      = (const float*)d_in[4];
    const float* bih      = (const float*)d_in[5];
    const float* bhh      = (const float*)d_in[6];
    const float* fcw      = (const float*)d_in[7];
    const float* fcb      = (const float*)d_in[8];
    float*       out      = (float*)d_out;

    cudaFuncSetAttribute(lstm_main_kernel,
                         cudaFuncAttributeMaxDynamicSharedMemorySize, SMEM_BYTES);
    cudaFuncSetAttribute(fc_kernel,
                         cudaFuncAttributeMaxDynamicSharedMemorySize, FC_SMEM_FLOATS * 4);

    zero_done_kernel<<<16, 256>>>();
    build_table_kernel<<<(VOCAB * G + 255) / 256, 256>>>(emb, Wih0, bih, bhh);
    lstm_main_kernel<<<LAYERS * NC, THR, SMEM_BYTES>>>(x, Wih_rest, Whh, bih, bhh);
    fc_kernel<<<T, 256, FC_SMEM_FLOATS * 4>>>(fcw, fcb, out);
}

// round 15
// speedup vs baseline: 4.9482x; 1.2987x over previous
#include <cuda_runtime.h>
#include <cuda_fp16.h>
#include <cstdint>

#define LAYERS 8
#define T      512
#define B      64
#define H      256
#define G      1024
#define VOCAB  23
#define EMB    16
#define NC     16
#define THR    256

#define WSTR   528            // bytes per padded row (264 fp16)

// smem byte offsets
#define SB_BUF0   0           // staging h plane / transient W prep
#define SB_BUF1   33792
#define SB_GX     67584       // f32 [64][68]
#define SB_GX2    84992       // f32 [64][68]
#define SB_CST    102400      // f32 [16][68]
#define SB_TAB    106752      // float4 [23*16]
#define SB_BIAS   112640      // float4 [16]
#define SB_TOK    112896      // int [64]
#define SMEM_BYTES 113152

static __device__ __align__(128) __half g_hbf[(size_t)LAYERS * T * 16384];   // [l][t][b][k] fp16
static __device__ float g_hseq7[(size_t)T * H * B];
static __device__ float g_table[VOCAB * G];
static __device__ int   g_done[LAYERS * T];

// ---------- helpers ----------
__device__ __forceinline__ uint32_t smem_u32(const void* p) {
    uint32_t a;
    asm("{ .reg .u64 t; cvta.to.shared.u64 t, %1; cvt.u32.u64 %0, t; }" : "=r"(a) : "l"(p));
    return a;
}
__device__ __forceinline__ float tanha(float x) {
    float y; asm("tanh.approx.f32 %0, %1;" : "=f"(y) : "f"(x));
    return y;
}
__device__ __forceinline__ float sigm(float x) { return fmaf(0.5f, tanha(0.5f * x), 0.5f); }

__device__ __forceinline__ void wait_done(int idx) {
    if (threadIdx.x == 0) {
        volatile int* p = &g_done[idx];
        while (*p < NC) __nanosleep(32);
    }
    __syncthreads();
}

#define LDSM4(r0,r1,r2,r3,addr) \
    asm volatile("ldmatrix.sync.aligned.m8n8.x4.shared.b16 {%0,%1,%2,%3}, [%4];" \
                 : "=r"(r0),"=r"(r1),"=r"(r2),"=r"(r3) : "r"(addr))

#define MMA16816(c, a0,a1,a2,a3, b0,b1) \
    asm volatile("mma.sync.aligned.m16n8k16.row.col.f32.f16.f16.f32 " \
                 "{%0,%1,%2,%3},{%4,%5,%6,%7},{%8,%9},{%0,%1,%2,%3};" \
                 : "+f"((c)[0]),"+f"((c)[1]),"+f"((c)[2]),"+f"((c)[3]) \
                 : "r"(a0),"r"(a1),"r"(a2),"r"(a3),"r"(b0),"r"(b1))

// Load this warp's persisted W fragments (8 k16 x 8 regs) from a padded smem plane.
__device__ __forceinline__ void load_wfrags(uint32_t (&wa)[8][8], uint32_t planeP, uint32_t ar) {
#pragma unroll
    for (int k = 0; k < 8; ++k) {
        LDSM4(wa[k][0],wa[k][1],wa[k][2],wa[k][3], planeP + ar + k * 32);
        LDSM4(wa[k][4],wa[k][5],wa[k][6],wa[k][7], planeP + ar + 16 * WSTR + k * 32);
    }
}

// Single-term pass: acc += W(regs) * B(smem) over 8 k16 chunks; B double-buffered.
__device__ __forceinline__ void pass1t(
    const uint32_t (&wa)[8][8], uint32_t bufP, float (&acc)[2][4][4], uint32_t br)
{
    const uint32_t bP = bufP + br;
    uint32_t fb[2][8];
    LDSM4(fb[0][0],fb[0][1],fb[0][2],fb[0][3], bP);
    LDSM4(fb[0][4],fb[0][5],fb[0][6],fb[0][7], bP + 16 * WSTR);
#pragma unroll
    for (int k = 0; k < 8; ++k) {
        const int cur = k & 1;
        if (k < 7) {
            const int nx = cur ^ 1;
            LDSM4(fb[nx][0],fb[nx][1],fb[nx][2],fb[nx][3], bP + (k+1)*32);
            LDSM4(fb[nx][4],fb[nx][5],fb[nx][6],fb[nx][7], bP + 16*WSTR + (k+1)*32);
        }
#pragma unroll
        for (int mh = 0; mh < 2; ++mh) {
            const uint32_t* ah = &wa[k][mh * 4];
            const uint32_t* b  = fb[cur];
            MMA16816(acc[mh][0], ah[0],ah[1],ah[2],ah[3], b[0],b[2]);
            MMA16816(acc[mh][1], ah[0],ah[1],ah[2],ah[3], b[1],b[3]);
            MMA16816(acc[mh][2], ah[0],ah[1],ah[2],ah[3], b[4],b[6]);
            MMA16816(acc[mh][3], ah[0],ah[1],ah[2],ah[3], b[5],b[7]);
        }
    }
}

// async-stage one dense 32KB global plane into a padded smem plane; commits a group.
__device__ __forceinline__ void stage(uint32_t dstS, const char* src, int tid) {
#pragma unroll
    for (int u = 0; u < 8; ++u) {
        int i = tid + u * THR;
        int b = i >> 5, kc = i & 31;
        asm volatile("cp.async.cg.shared.global [%0], [%1], 16;"
                     :: "r"(dstS + (uint32_t)(b * WSTR + kc * 16)),
                        "l"(src + b * 512 + kc * 16) : "memory");
    }
    asm volatile("cp.async.commit_group;" ::: "memory");
}
#define CP_WAIT1() asm volatile("cp.async.wait_group 1;" ::: "memory")
#define CP_WAIT0() asm volatile("cp.async.wait_group 0;" ::: "memory")

// ---------- prelude ----------
__global__ void zero_done_kernel() {
    int i = blockIdx.x * blockDim.x + threadIdx.x;
    if (i < LAYERS * T) g_done[i] = 0;
}
__global__ void build_table_kernel(const float* __restrict__ emb, const float* __restrict__ Wih0,
                                   const float* __restrict__ bih, const float* __restrict__ bhh) {
    int idx = blockIdx.x * blockDim.x + threadIdx.x;
    if (idx >= VOCAB * G) return;
    int v = idx / G, j = idx % G;
    float s = bih[j] + bhh[j];
#pragma unroll
    for (int e = 0; e < EMB; ++e) s += emb[v * EMB + e] * Wih0[j * EMB + e];
    g_table[idx] = s;
}

// ---------- main persistent wavefront kernel ----------
extern "C" __global__ void __launch_bounds__(THR, 1)
lstm_main_kernel(const int* __restrict__ x,
                 const float* __restrict__ Wih_rest,
                 const float* __restrict__ Whh,
                 const float* __restrict__ bih,
                 const float* __restrict__ bhh)
{
    extern __shared__ char smem[];
    const uint32_t sb = smem_u32(smem);
    const int tid  = threadIdx.x;
    const int warp = tid >> 5, lane = tid & 31;
    const int l = blockIdx.x >> 4;
    const int c = blockIdx.x & 15;          // unit block: units c*16 .. c*16+15
    const int kh = warp >> 2, mi = (warp >> 1) & 1, ni = warp & 1;

    float*  gx    = (float*)(smem + SB_GX);     // [64][68]
    float*  gx2   = (float*)(smem + SB_GX2);    // [64][68]
    float*  cst   = (float*)(smem + SB_CST);    // [16][68]
    float4* tab4  = (float4*)(smem + SB_TAB);
    float4* bias4 = (float4*)(smem + SB_BIAS);
    int*    tokI  = (int*)(smem + SB_TOK);

    // per-warp fragment base offsets
    const uint32_t kOff = (uint32_t)(kh * 256) + ((lane >> 4) << 4);
    const uint32_t ar = (uint32_t)(mi * 32 + (lane & 15)) * WSTR + kOff;
    const uint32_t br = (uint32_t)(ni * 32 + (lane & 15)) * WSTR + kOff;

    // ---- weight prep: fp16 W -> BUF0/BUF1 (transient) ----
    {
        const float* Wl = Whh + (size_t)l * G * H;
        for (int idx = tid; idx < 64 * 256; idx += THR) {
            int r = idx >> 8, k = idx & 255;
            int jg = (r >> 4) * H + c * 16 + (r & 15);
            *(__half*)(smem + SB_BUF0 + r * WSTR + k * 2) =
                __float2half_rn(Wl[(size_t)jg * H + k]);
        }
    }
    if (l > 0) {
        const float* Wl = Wih_rest + (size_t)(l - 1) * G * H;
        for (int idx = tid; idx < 64 * 256; idx += THR) {
            int r = idx >> 8, k = idx & 255;
            int jg = (r >> 4) * H + c * 16 + (r & 15);
            *(__half*)(smem + SB_BUF1 + r * WSTR + k * 2) =
                __float2half_rn(Wl[(size_t)jg * H + k]);
        }
        if (tid < 16) {
            int u = tid;
            float4 q;
            q.x = bih[l * G + 0 * H + c * 16 + u] + bhh[l * G + 0 * H + c * 16 + u];
            q.y = bih[l * G + 1 * H + c * 16 + u] + bhh[l * G + 1 * H + c * 16 + u];
            q.z = bih[l * G + 2 * H + c * 16 + u] + bhh[l * G + 2 * H + c * 16 + u];
            q.w = bih[l * G + 3 * H + c * 16 + u] + bhh[l * G + 3 * H + c * 16 + u];
            bias4[u] = q;
        }
    } else {
        for (int idx = tid; idx < VOCAB * 16; idx += THR) {
            int v = idx >> 4, u = idx & 15;
            float4 q;
            q.x = g_table[v * G + 0 * H + c * 16 + u];
            q.y = g_table[v * G + 1 * H + c * 16 + u];
            q.z = g_table[v * G + 2 * H + c * 16 + u];
            q.w = g_table[v * G + 3 * H + c * 16 + u];
            tab4[idx] = q;
        }
    }
    __syncthreads();

    // ---- persist W fragments in registers for the whole run ----
    uint32_t whh_w[8][8], wih_w[8][8];
    load_wfrags(whh_w, sb + SB_BUF0, ar);
    if (l > 0) load_wfrags(wih_w, sb + SB_BUF1, ar);
    else {
#pragma unroll
        for (int k = 0; k < 8; ++k)
#pragma unroll
            for (int j = 0; j < 8; ++j) wih_w[k][j] = 0;
    }
    __syncthreads();   // BUF0/BUF1 free for staging

    for (int t = 0; t < T; ++t) {
        if (l == 0 && tid < 64) tokI[tid] = x[tid * T + t];

        float acc[2][4][4];
#pragma unroll
        for (int a = 0; a < 2; ++a)
#pragma unroll
            for (int b = 0; b < 4; ++b)
#pragma unroll
                for (int q = 0; q < 4; ++q) acc[a][b][q] = 0.f;

        const bool rec = (t > 0), inp = (l > 0);
        const char* recsrc = (const char*)g_hbf + (size_t)(l * T + t - 1) * 32768;
        const char* insrc  = (const char*)g_hbf + (size_t)((l - 1) * T + t) * 32768;

        if (rec && inp) {
            wait_done(l * T + (t - 1));
            stage(sb + SB_BUF0, recsrc, tid);                 // G1 rec_h
            wait_done((l - 1) * T + t);
            stage(sb + SB_BUF1, insrc, tid);                  // G2 in_h
            CP_WAIT1(); __syncthreads();                      // buf0 ready
            pass1t(whh_w, sb + SB_BUF0, acc, br);
            CP_WAIT0(); __syncthreads();                      // buf1 ready
            pass1t(wih_w, sb + SB_BUF1, acc, br);
        } else if (rec) {
            wait_done(l * T + (t - 1));
            stage(sb + SB_BUF0, recsrc, tid);
            CP_WAIT0(); __syncthreads();
            pass1t(whh_w, sb + SB_BUF0, acc, br);
        } else if (inp) {
            wait_done((l - 1) * T + t);
            stage(sb + SB_BUF0, insrc, tid);
            CP_WAIT0(); __syncthreads();
            pass1t(wih_w, sb + SB_BUF0, acc, br);
        }

        // ---- split-K store (kh=0 -> gx, kh=1 -> gx2), then single barrier ----
        {
            float* dst = (kh == 0) ? gx : gx2;
#pragma unroll
            for (int ms = 0; ms < 2; ++ms) {
                int m = mi * 32 + ms * 16 + (lane >> 2);
#pragma unroll
                for (int ns = 0; ns < 4; ++ns) {
                    int b = ni * 32 + ns * 8 + (lane & 3) * 2;
                    *(float2*)(dst + m * 68 + b)       = make_float2(acc[ms][ns][0], acc[ms][ns][1]);
                    *(float2*)(dst + (m + 8) * 68 + b) = make_float2(acc[ms][ns][2], acc[ms][ns][3]);
                }
            }
        }
        __syncthreads();   // gx/gx2 visible; BUF reads done before next-step staging

        // ---- cell update: thread = (u, 4 b's); coalesced fp16 h publish ----
        {
            const int u = tid & 15, grp = tid >> 4;
            char* dstP = (char*)g_hbf + (size_t)(l * T + t) * 32768;
            const int k = c * 16 + u;
            float4 bq = (l > 0) ? bias4[u] : make_float4(0.f, 0.f, 0.f, 0.f);
#pragma unroll
            for (int i = 0; i < 4; ++i) {
                int b = grp * 4 + i;
                float4 q = (l == 0) ? tab4[tokI[b] * 16 + u] : bq;
                float ig = gx[(0 * 16 + u) * 68 + b] + gx2[(0 * 16 + u) * 68 + b] + q.x;
                float fg = gx[(1 * 16 + u) * 68 + b] + gx2[(1 * 16 + u) * 68 + b] + q.y;
                float gg = gx[(2 * 16 + u) * 68 + b] + gx2[(2 * 16 + u) * 68 + b] + q.z;
                float og = gx[(3 * 16 + u) * 68 + b] + gx2[(3 * 16 + u) * 68 + b] + q.w;
                float cv = (t == 0) ? 0.f : cst[u * 68 + b];
                float cn = sigm(fg) * cv + sigm(ig) * tanha(gg);
                cst[u * 68 + b] = cn;
                float hv = sigm(og) * tanha(cn);
                *(__half*)(dstP + b * 512 + k * 2) = __float2half_rn(hv);
                if (l == 7) g_hseq7[(size_t)t * 16384 + k * 64 + b] = hv;
            }
        }
        __threadfence();
        __syncthreads();
        if (tid == 0) atomicAdd(&g_done[l * T + t], 1);
    }
}

// ---------- final FC ----------
#define FC_SMEM_FLOATS (256 * 64 + 256 * 24 + 32)
__global__ void __launch_bounds__(256)
fc_kernel(const float* __restrict__ fcw, const float* __restrict__ fcb,
          float* __restrict__ out)
{
    extern __shared__ float fsm[];
    float* hs = fsm;
    float* ws = fsm + 256 * 64;
    float* bs = ws + 256 * 24;
    const int tid = threadIdx.x, t = blockIdx.x;

    const float* h7 = g_hseq7 + (size_t)t * H * B;
    {
        const float4* s = (const float4*)h7;
        float4* d = (float4*)hs;
        for (int i = tid; i < 4096; i += 256) d[i] = s[i];
    }
    for (int i = tid; i < VOCAB * H; i += 256) {
        int v = i >> 8, k = i & 255;
        ws[k * 24 + v] = fcw[i];
    }
    if (tid < VOCAB) bs[tid] = fcb[tid];
    __syncthreads();

    const int b = tid & 63, vg = tid >> 6;
    const int v0 = vg * 6;
    const int nv = (v0 + 6 <= VOCAB) ? 6 : (VOCAB - v0);
    float acc[6] = {0.f, 0.f, 0.f, 0.f, 0.f, 0.f};
#pragma unroll 4
    for (int k = 0; k < 256; ++k) {
        float a = hs[k * 64 + b];
#pragma unroll
        for (int j = 0; j < 6; ++j) acc[j] += a * ws[k * 24 + v0 + j];
    }
    for (int j = 0; j < nv; ++j)
        out[((size_t)b * T + t) * VOCAB + v0 + j] = acc[j] + bs[v0 + j];
}

// ---------- launch ----------
extern "C" void kernel_launch(void* const* d_in, const int* in_sizes, int n_in,
                              void* d_out, int out_size)
{
    const int*   x        = (const int*)d_in[0];
    const float* emb      = (const float*)d_in[1];
    const float* Wih0     = (const float*)d_in[2];
    const float* Wih_rest = (const float*)d_in[3];
    const float* Whh      = (const float*)d_in[4];
    const float* bih      = (const float*)d_in[5];
    const float* bhh      = (const float*)d_in[6];
    const float* fcw      = (const float*)d_in[7];
    const float* fcb      = (const float*)d_in[8];
    float*       out      = (float*)d_out;

    cudaFuncSetAttribute(lstm_main_kernel,
                         cudaFuncAttributeMaxDynamicSharedMemorySize, SMEM_BYTES);
    cudaFuncSetAttribute(fc_kernel,
                         cudaFuncAttributeMaxDynamicSharedMemorySize, FC_SMEM_FLOATS * 4);

    zero_done_kernel<<<16, 256>>>();
    build_table_kernel<<<(VOCAB * G + 255) / 256, 256>>>(emb, Wih0, bih, bhh);
    lstm_main_kernel<<<LAYERS * NC, THR, SMEM_BYTES>>>(x, Wih_rest, Whh, bih, bhh);
    fc_kernel<<<T, 256, FC_SMEM_FLOATS * 4>>>(fcw, fcb, out);
}

// round 16
// speedup vs baseline: 5.2040x; 1.0517x over previous
#include <cuda_runtime.h>
#include <cuda_fp16.h>
#include <cstdint>

#define LAYERS 8
#define T      512
#define B      64
#define H      256
#define G      1024
#define VOCAB  23
#define EMB    16
#define NC     16
#define THR    256

#define WSTR   528            // bytes per padded row (264 fp16)

// smem byte offsets
#define SB_BUF0   0           // staging h plane / transient W prep
#define SB_BUF1   33792
#define SB_GX     67584       // f32 [64][68]
#define SB_GX2    84992       // f32 [64][68]
#define SB_CST    102400      // f32 [16][68]
#define SB_TAB    106752      // float4 [23*16]
#define SB_BIAS   112640      // float4 [16]
#define SB_TOK    112896      // int [64]
#define SMEM_BYTES 113152

static __device__ __align__(128) __half g_hbf[(size_t)LAYERS * T * 16384];   // [l][t][b][k] fp16
static __device__ float g_hseq7[(size_t)T * H * B];
static __device__ float g_table[VOCAB * G];
static __device__ int   g_prog[LAYERS * NC];    // per-CTA progress: steps completed

// ---------- helpers ----------
__device__ __forceinline__ uint32_t smem_u32(const void* p) {
    uint32_t a;
    asm("{ .reg .u64 t; cvta.to.shared.u64 t, %1; cvt.u32.u64 %0, t; }" : "=r"(a) : "l"(p));
    return a;
}
__device__ __forceinline__ float tanha(float x) {
    float y; asm("tanh.approx.f32 %0, %1;" : "=f"(y) : "f"(x));
    return y;
}
__device__ __forceinline__ float sigm(float x) { return fmaf(0.5f, tanha(0.5f * x), 0.5f); }

// wait until all NC CTAs of `layer` have completed `val` steps
__device__ __forceinline__ void wait_prog(int layer, int val, int tid) {
    if (tid < NC) {
        volatile int* p = &g_prog[layer * NC + tid];
        while (*p < val) __nanosleep(32);
    }
    __syncthreads();
}

#define LDSM4(r0,r1,r2,r3,addr) \
    asm volatile("ldmatrix.sync.aligned.m8n8.x4.shared.b16 {%0,%1,%2,%3}, [%4];" \
                 : "=r"(r0),"=r"(r1),"=r"(r2),"=r"(r3) : "r"(addr))

#define MMA16816(c, a0,a1,a2,a3, b0,b1) \
    asm volatile("mma.sync.aligned.m16n8k16.row.col.f32.f16.f16.f32 " \
                 "{%0,%1,%2,%3},{%4,%5,%6,%7},{%8,%9},{%0,%1,%2,%3};" \
                 : "+f"((c)[0]),"+f"((c)[1]),"+f"((c)[2]),"+f"((c)[3]) \
                 : "r"(a0),"r"(a1),"r"(a2),"r"(a3),"r"(b0),"r"(b1))

// Load this warp's persisted W fragments (8 k16 x 8 regs) from a padded smem plane.
__device__ __forceinline__ void load_wfrags(uint32_t (&wa)[8][8], uint32_t planeP, uint32_t ar) {
#pragma unroll
    for (int k = 0; k < 8; ++k) {
        LDSM4(wa[k][0],wa[k][1],wa[k][2],wa[k][3], planeP + ar + k * 32);
        LDSM4(wa[k][4],wa[k][5],wa[k][6],wa[k][7], planeP + ar + 16 * WSTR + k * 32);
    }
}

// Single-term pass: acc += W(regs) * B(smem) over 8 k16 chunks; B double-buffered.
__device__ __forceinline__ void pass1t(
    const uint32_t (&wa)[8][8], uint32_t bufP, float (&acc)[2][4][4], uint32_t br)
{
    const uint32_t bP = bufP + br;
    uint32_t fb[2][8];
    LDSM4(fb[0][0],fb[0][1],fb[0][2],fb[0][3], bP);
    LDSM4(fb[0][4],fb[0][5],fb[0][6],fb[0][7], bP + 16 * WSTR);
#pragma unroll
    for (int k = 0; k < 8; ++k) {
        const int cur = k & 1;
        if (k < 7) {
            const int nx = cur ^ 1;
            LDSM4(fb[nx][0],fb[nx][1],fb[nx][2],fb[nx][3], bP + (k+1)*32);
            LDSM4(fb[nx][4],fb[nx][5],fb[nx][6],fb[nx][7], bP + 16*WSTR + (k+1)*32);
        }
#pragma unroll
        for (int mh = 0; mh < 2; ++mh) {
            const uint32_t* ah = &wa[k][mh * 4];
            const uint32_t* b  = fb[cur];
            MMA16816(acc[mh][0], ah[0],ah[1],ah[2],ah[3], b[0],b[2]);
            MMA16816(acc[mh][1], ah[0],ah[1],ah[2],ah[3], b[1],b[3]);
            MMA16816(acc[mh][2], ah[0],ah[1],ah[2],ah[3], b[4],b[6]);
            MMA16816(acc[mh][3], ah[0],ah[1],ah[2],ah[3], b[5],b[7]);
        }
    }
}

// async-stage one dense 32KB global plane into a padded smem plane; commits a group.
__device__ __forceinline__ void stage(uint32_t dstS, const char* src, int tid) {
#pragma unroll
    for (int u = 0; u < 8; ++u) {
        int i = tid + u * THR;
        int b = i >> 5, kc = i & 31;
        asm volatile("cp.async.cg.shared.global [%0], [%1], 16;"
                     :: "r"(dstS + (uint32_t)(b * WSTR + kc * 16)),
                        "l"(src + b * 512 + kc * 16) : "memory");
    }
    asm volatile("cp.async.commit_group;" ::: "memory");
}
#define CP_WAIT1() asm volatile("cp.async.wait_group 1;" ::: "memory")
#define CP_WAIT0() asm volatile("cp.async.wait_group 0;" ::: "memory")

// ---------- prelude ----------
__global__ void zero_prog_kernel() {
    int i = blockIdx.x * blockDim.x + threadIdx.x;
    if (i < LAYERS * NC) g_prog[i] = 0;
}
__global__ void build_table_kernel(const float* __restrict__ emb, const float* __restrict__ Wih0,
                                   const float* __restrict__ bih, const float* __restrict__ bhh) {
    int idx = blockIdx.x * blockDim.x + threadIdx.x;
    if (idx >= VOCAB * G) return;
    int v = idx / G, j = idx % G;
    float s = bih[j] + bhh[j];
#pragma unroll
    for (int e = 0; e < EMB; ++e) s += emb[v * EMB + e] * Wih0[j * EMB + e];
    g_table[idx] = s;
}

// ---------- main persistent wavefront kernel ----------
extern "C" __global__ void __launch_bounds__(THR, 1)
lstm_main_kernel(const int* __restrict__ x,
                 const float* __restrict__ Wih_rest,
                 const float* __restrict__ Whh,
                 const float* __restrict__ bih,
                 const float* __restrict__ bhh)
{
    extern __shared__ char smem[];
    const uint32_t sb = smem_u32(smem);
    const int tid  = threadIdx.x;
    const int warp = tid >> 5, lane = tid & 31;
    const int l = blockIdx.x >> 4;
    const int c = blockIdx.x & 15;          // unit block: units c*16 .. c*16+15
    const int kh = warp >> 2, mi = (warp >> 1) & 1, ni = warp & 1;

    float*  gx    = (float*)(smem + SB_GX);     // [64][68]
    float*  gx2   = (float*)(smem + SB_GX2);    // [64][68]
    float*  cst   = (float*)(smem + SB_CST);    // [16][68]
    float4* tab4  = (float4*)(smem + SB_TAB);
    float4* bias4 = (float4*)(smem + SB_BIAS);
    int*    tokI  = (int*)(smem + SB_TOK);

    // per-warp fragment base offsets
    const uint32_t kOff = (uint32_t)(kh * 256) + ((lane >> 4) << 4);
    const uint32_t ar = (uint32_t)(mi * 32 + (lane & 15)) * WSTR + kOff;
    const uint32_t br = (uint32_t)(ni * 32 + (lane & 15)) * WSTR + kOff;

    // ---- weight prep: fp16 W -> BUF0/BUF1 (transient) ----
    {
        const float* Wl = Whh + (size_t)l * G * H;
        for (int idx = tid; idx < 64 * 256; idx += THR) {
            int r = idx >> 8, k = idx & 255;
            int jg = (r >> 4) * H + c * 16 + (r & 15);
            *(__half*)(smem + SB_BUF0 + r * WSTR + k * 2) =
                __float2half_rn(Wl[(size_t)jg * H + k]);
        }
    }
    if (l > 0) {
        const float* Wl = Wih_rest + (size_t)(l - 1) * G * H;
        for (int idx = tid; idx < 64 * 256; idx += THR) {
            int r = idx >> 8, k = idx & 255;
            int jg = (r >> 4) * H + c * 16 + (r & 15);
            *(__half*)(smem + SB_BUF1 + r * WSTR + k * 2) =
                __float2half_rn(Wl[(size_t)jg * H + k]);
        }
        if (tid < 16) {
            int u = tid;
            float4 q;
            q.x = bih[l * G + 0 * H + c * 16 + u] + bhh[l * G + 0 * H + c * 16 + u];
            q.y = bih[l * G + 1 * H + c * 16 + u] + bhh[l * G + 1 * H + c * 16 + u];
            q.z = bih[l * G + 2 * H + c * 16 + u] + bhh[l * G + 2 * H + c * 16 + u];
            q.w = bih[l * G + 3 * H + c * 16 + u] + bhh[l * G + 3 * H + c * 16 + u];
            bias4[u] = q;
        }
    } else {
        for (int idx = tid; idx < VOCAB * 16; idx += THR) {
            int v = idx >> 4, u = idx & 15;
            float4 q;
            q.x = g_table[v * G + 0 * H + c * 16 + u];
            q.y = g_table[v * G + 1 * H + c * 16 + u];
            q.z = g_table[v * G + 2 * H + c * 16 + u];
            q.w = g_table[v * G + 3 * H + c * 16 + u];
            tab4[idx] = q;
        }
    }
    __syncthreads();

    // ---- persist W fragments in registers for the whole run ----
    uint32_t whh_w[8][8], wih_w[8][8];
    load_wfrags(whh_w, sb + SB_BUF0, ar);
    if (l > 0) load_wfrags(wih_w, sb + SB_BUF1, ar);
    else {
#pragma unroll
        for (int k = 0; k < 8; ++k)
#pragma unroll
            for (int j = 0; j < 8; ++j) wih_w[k][j] = 0;
    }
    __syncthreads();   // BUF0/BUF1 free for staging

    for (int t = 0; t < T; ++t) {
        if (l == 0 && tid < 64) tokI[tid] = x[tid * T + t];

        float acc[2][4][4];
#pragma unroll
        for (int a = 0; a < 2; ++a)
#pragma unroll
            for (int b = 0; b < 4; ++b)
#pragma unroll
                for (int q = 0; q < 4; ++q) acc[a][b][q] = 0.f;

        const bool rec = (t > 0), inp = (l > 0);
        const char* recsrc = (const char*)g_hbf + (size_t)(l * T + t - 1) * 32768;
        const char* insrc  = (const char*)g_hbf + (size_t)((l - 1) * T + t) * 32768;

        if (rec && inp) {
            // input dependency is usually ready (producer runs ahead) — stage it first,
            // then overlap rec staging with the input pass.
            wait_prog(l - 1, t + 1, tid);
            stage(sb + SB_BUF1, insrc, tid);                  // G1 in_h
            wait_prog(l, t, tid);
            stage(sb + SB_BUF0, recsrc, tid);                 // G2 rec_h
            CP_WAIT1(); __syncthreads();                      // buf1 (in_h) ready
            pass1t(wih_w, sb + SB_BUF1, acc, br);             // rec staging in flight
            CP_WAIT0(); __syncthreads();                      // buf0 (rec_h) ready
            pass1t(whh_w, sb + SB_BUF0, acc, br);
        } else if (rec) {
            wait_prog(l, t, tid);
            stage(sb + SB_BUF0, recsrc, tid);
            CP_WAIT0(); __syncthreads();
            pass1t(whh_w, sb + SB_BUF0, acc, br);
        } else if (inp) {
            wait_prog(l - 1, t + 1, tid);
            stage(sb + SB_BUF0, insrc, tid);
            CP_WAIT0(); __syncthreads();
            pass1t(wih_w, sb + SB_BUF0, acc, br);
        }

        // ---- split-K store (kh=0 -> gx, kh=1 -> gx2), then single barrier ----
        {
            float* dst = (kh == 0) ? gx : gx2;
#pragma unroll
            for (int ms = 0; ms < 2; ++ms) {
                int m = mi * 32 + ms * 16 + (lane >> 2);
#pragma unroll
                for (int ns = 0; ns < 4; ++ns) {
                    int b = ni * 32 + ns * 8 + (lane & 3) * 2;
                    *(float2*)(dst + m * 68 + b)       = make_float2(acc[ms][ns][0], acc[ms][ns][1]);
                    *(float2*)(dst + (m + 8) * 68 + b) = make_float2(acc[ms][ns][2], acc[ms][ns][3]);
                }
            }
        }
        __syncthreads();   // gx/gx2 visible; BUF reads done before next-step staging

        // ---- cell update: thread = (u, 4 b's); coalesced fp16 h publish ----
        {
            const int u = tid & 15, grp = tid >> 4;
            char* dstP = (char*)g_hbf + (size_t)(l * T + t) * 32768;
            const int k = c * 16 + u;
            float4 bq = (l > 0) ? bias4[u] : make_float4(0.f, 0.f, 0.f, 0.f);
#pragma unroll
            for (int i = 0; i < 4; ++i) {
                int b = grp * 4 + i;
                float4 q = (l == 0) ? tab4[tokI[b] * 16 + u] : bq;
                float ig = gx[(0 * 16 + u) * 68 + b] + gx2[(0 * 16 + u) * 68 + b] + q.x;
                float fg = gx[(1 * 16 + u) * 68 + b] + gx2[(1 * 16 + u) * 68 + b] + q.y;
                float gg = gx[(2 * 16 + u) * 68 + b] + gx2[(2 * 16 + u) * 68 + b] + q.z;
                float og = gx[(3 * 16 + u) * 68 + b] + gx2[(3 * 16 + u) * 68 + b] + q.w;
                float cv = (t == 0) ? 0.f : cst[u * 68 + b];
                float cn = sigm(fg) * cv + sigm(ig) * tanha(gg);
                cst[u * 68 + b] = cn;
                float hv = sigm(og) * tanha(cn);
                *(__half*)(dstP + b * 512 + k * 2) = __float2half_rn(hv);
                if (l == 7) g_hseq7[(size_t)t * 16384 + k * 64 + b] = hv;
            }
        }
        __syncthreads();                 // all h stores issued
        if (tid == 0) {
            __threadfence();             // fence in one thread only (after barrier)
            *(volatile int*)&g_prog[l * NC + c] = t + 1;
        }
    }
}

// ---------- final FC ----------
#define FC_SMEM_FLOATS (256 * 64 + 256 * 24 + 32)
__global__ void __launch_bounds__(256)
fc_kernel(const float* __restrict__ fcw, const float* __restrict__ fcb,
          float* __restrict__ out)
{
    extern __shared__ float fsm[];
    float* hs = fsm;
    float* ws = fsm + 256 * 64;
    float* bs = ws + 256 * 24;
    const int tid = threadIdx.x, t = blockIdx.x;

    const float* h7 = g_hseq7 + (size_t)t * H * B;
    {
        const float4* s = (const float4*)h7;
        float4* d = (float4*)hs;
        for (int i = tid; i < 4096; i += 256) d[i] = s[i];
    }
    for (int i = tid; i < VOCAB * H; i += 256) {
        int v = i >> 8, k = i & 255;
        ws[k * 24 + v] = fcw[i];
    }
    if (tid < VOCAB) bs[tid] = fcb[tid];
    __syncthreads();

    const int b = tid & 63, vg = tid >> 6;
    const int v0 = vg * 6;
    const int nv = (v0 + 6 <= VOCAB) ? 6 : (VOCAB - v0);
    float acc[6] = {0.f, 0.f, 0.f, 0.f, 0.f, 0.f};
#pragma unroll 4
    for (int k = 0; k < 256; ++k) {
        float a = hs[k * 64 + b];
#pragma unroll
        for (int j = 0; j < 6; ++j) acc[j] += a * ws[k * 24 + v0 + j];
    }
    for (int j = 0; j < nv; ++j)
        out[((size_t)b * T + t) * VOCAB + v0 + j] = acc[j] + bs[v0 + j];
}

// ---------- launch ----------
extern "C" void kernel_launch(void* const* d_in, const int* in_sizes, int n_in,
                              void* d_out, int out_size)
{
    const int*   x        = (const int*)d_in[0];
    const float* emb      = (const float*)d_in[1];
    const float* Wih0     = (const float*)d_in[2];
    const float* Wih_rest = (const float*)d_in[3];
    const float* Whh      = (const float*)d_in[4];
    const float* bih      = (const float*)d_in[5];
    const float* bhh      = (const float*)d_in[6];
    const float* fcw      = (const float*)d_in[7];
    const float* fcb      = (const float*)d_in[8];
    float*       out      = (float*)d_out;

    cudaFuncSetAttribute(lstm_main_kernel,
                         cudaFuncAttributeMaxDynamicSharedMemorySize, SMEM_BYTES);
    cudaFuncSetAttribute(fc_kernel,
                         cudaFuncAttributeMaxDynamicSharedMemorySize, FC_SMEM_FLOATS * 4);

    zero_prog_kernel<<<1, 256>>>();
    build_table_kernel<<<(VOCAB * G + 255) / 256, 256>>>(emb, Wih0, bih, bhh);
    lstm_main_kernel<<<LAYERS * NC, THR, SMEM_BYTES>>>(x, Wih_rest, Whh, bih, bhh);
    fc_kernel<<<T, 256, FC_SMEM_FLOATS * 4>>>(fcw, fcb, out);
}